// round 2
// baseline (speedup 1.0000x reference)
#include <cuda_runtime.h>
#include <cuda_bf16.h>
#include <math.h>

#define BATCH 8
#define SEQ   1024
#define DIMC  768
#define NH    12
#define HD    64
#define M_TOT (BATCH*SEQ)     /* 8192 */
#define QK_SCALE 0.125f       /* 64^-0.5 */

/* ---------------- scratch (no cudaMalloc allowed) ---------------- */
__device__ float g_q[BATCH*NH*SEQ*HD];   /* [bh][n][d], q pre-scaled */
__device__ float g_k[BATCH*NH*SEQ*HD];
__device__ float g_v[BATCH*NH*SEQ*HD];
__device__ float g_ao[M_TOT*DIMC];       /* attention out in [B,N,C] */
__device__ int   g_mask_is_byte;

/* ---------------- mask dtype sniffing ----------------
   bool serialization -> ~half of bytes at i%4!=0 are nonzero.
   int32 serialization (values 0/1 LE) -> those bytes are all zero. */
__global__ void detect_mask_kernel(const unsigned char* __restrict__ m) {
    __shared__ int any;
    if (threadIdx.x == 0) any = 0;
    __syncthreads();
    int loc = 0;
    for (int i = threadIdx.x; i < BATCH*SEQ; i += blockDim.x)
        if ((i & 3) && m[i]) loc = 1;
    if (loc) any = 1;
    __syncthreads();
    if (threadIdx.x == 0) g_mask_is_byte = any;
}

/* ---------------- generic NT SGEMM: C[M,N] = A[M,768] * W[N,768]^T ----------------
   Double-buffered smem; global loads staged through registers so FFMAs
   overlap the LDG latency.
   MODE 0: QKV projection -> scatter into g_q (+q_bias, *scale), g_k, g_v (+v_bias)
   MODE 1: output projection (A := g_ao), +proj_b, write Cout. */
#define BM 128
#define BN 128
#define BKT 16
#define GPAD 4

template<int MODE>
__global__ void __launch_bounds__(256, 2) gemm_nt(
    const float* __restrict__ A, const float* __restrict__ W,
    const float* __restrict__ bias0, const float* __restrict__ bias1,
    float* __restrict__ Cout)
{
    __shared__ __align__(16) float As[2][BKT][BM + GPAD];
    __shared__ __align__(16) float Bs[2][BKT][BN + GPAD];

    const int tid = threadIdx.x;
    const int ty = tid >> 4, tx = tid & 15;
    const int bm = blockIdx.y * BM, bn = blockIdx.x * BN;

    const float* Ap = (MODE == 1) ? g_ao : A;

    /* each thread owns 2 float4 slots per operand */
    int r_[2], c_[2];
#pragma unroll
    for (int u = 0; u < 2; u++) {
        int idx = tid + u * 256;
        r_[u] = idx >> 2;
        c_[u] = (idx & 3) << 2;
    }

    float acc[8][8];
#pragma unroll
    for (int i = 0; i < 8; i++)
#pragma unroll
        for (int j = 0; j < 8; j++) acc[i][j] = 0.f;

    /* prologue: tile 0 into buffer 0 */
    float4 ra[2], rb[2];
#pragma unroll
    for (int u = 0; u < 2; u++) {
        ra[u] = *(const float4*)(Ap + (size_t)(bm + r_[u]) * 768 + c_[u]);
        rb[u] = *(const float4*)(W  + (size_t)(bn + r_[u]) * 768 + c_[u]);
    }
#pragma unroll
    for (int u = 0; u < 2; u++) {
        As[0][c_[u]+0][r_[u]] = ra[u].x; As[0][c_[u]+1][r_[u]] = ra[u].y;
        As[0][c_[u]+2][r_[u]] = ra[u].z; As[0][c_[u]+3][r_[u]] = ra[u].w;
        Bs[0][c_[u]+0][r_[u]] = rb[u].x; Bs[0][c_[u]+1][r_[u]] = rb[u].y;
        Bs[0][c_[u]+2][r_[u]] = rb[u].z; Bs[0][c_[u]+3][r_[u]] = rb[u].w;
    }
    __syncthreads();

    int buf = 0;
    for (int k0 = 0; k0 < 768; k0 += BKT) {
        const bool has_next = (k0 + BKT) < 768;
        if (has_next) {
            int kn = k0 + BKT;
#pragma unroll
            for (int u = 0; u < 2; u++) {
                ra[u] = *(const float4*)(Ap + (size_t)(bm + r_[u]) * 768 + kn + c_[u]);
                rb[u] = *(const float4*)(W  + (size_t)(bn + r_[u]) * 768 + kn + c_[u]);
            }
        }
#pragma unroll
        for (int k = 0; k < BKT; k++) {
            float a[8], b[8];
            *(float4*)&a[0] = *(const float4*)&As[buf][k][ty*8];
            *(float4*)&a[4] = *(const float4*)&As[buf][k][ty*8+4];
            *(float4*)&b[0] = *(const float4*)&Bs[buf][k][tx*8];
            *(float4*)&b[4] = *(const float4*)&Bs[buf][k][tx*8+4];
#pragma unroll
            for (int i = 0; i < 8; i++)
#pragma unroll
                for (int j = 0; j < 8; j++)
                    acc[i][j] += a[i] * b[j];
        }
        if (has_next) {
            int nb = buf ^ 1;
#pragma unroll
            for (int u = 0; u < 2; u++) {
                As[nb][c_[u]+0][r_[u]] = ra[u].x; As[nb][c_[u]+1][r_[u]] = ra[u].y;
                As[nb][c_[u]+2][r_[u]] = ra[u].z; As[nb][c_[u]+3][r_[u]] = ra[u].w;
                Bs[nb][c_[u]+0][r_[u]] = rb[u].x; Bs[nb][c_[u]+1][r_[u]] = rb[u].y;
                Bs[nb][c_[u]+2][r_[u]] = rb[u].z; Bs[nb][c_[u]+3][r_[u]] = rb[u].w;
            }
            __syncthreads();
            buf = nb;
        }
    }

    if (MODE == 1) {
#pragma unroll
        for (int i = 0; i < 8; i++) {
            int m = bm + ty*8 + i;
            float* op = Cout + (size_t)m * 768 + bn + tx*8;
#pragma unroll
            for (int j = 0; j < 8; j += 4) {
                float4 o;
                o.x = acc[i][j+0] + bias0[bn + tx*8 + j+0];
                o.y = acc[i][j+1] + bias0[bn + tx*8 + j+1];
                o.z = acc[i][j+2] + bias0[bn + tx*8 + j+2];
                o.w = acc[i][j+3] + bias0[bn + tx*8 + j+3];
                *(float4*)(op + j) = o;
            }
        }
    } else {
        /* n0..n0+7 all inside one (which, head) slot since 8 | 64 */
        int n0 = bn + tx*8;
        int which = n0 / 768;                 /* 0=q 1=k 2=v */
        int nn = n0 % 768;
        int h = nn / 64;
        int d0 = nn % 64;
        float* base = (which == 0) ? g_q : ((which == 1) ? g_k : g_v);
#pragma unroll
        for (int i = 0; i < 8; i++) {
            int m = bm + ty*8 + i;
            int b = m >> 10, tok = m & 1023;
            float* op = base + ((size_t)((b*NH + h)*SEQ + tok)) * HD + d0;
#pragma unroll
            for (int j = 0; j < 8; j++) {
                float v = acc[i][j];
                if (which == 0)       v = (v + bias0[nn + j]) * QK_SCALE;
                else if (which == 2)  v = v + bias1[nn + j];
                op[j] = v;
            }
        }
    }
}

/* ---------------- flash attention: one CTA per (bh, 64-row q tile) ----------------
   Qs/Ks stored d-major ([64 d][68]) so S = Q K^T reads both operands as LDS.128.
   Vs normal ([64 k][68]), P staged in smem for the P*V pass. */
#define FPAD 68
#define FLASH_SMEM ((4*64*FPAD + 64) * 4)   /* 69888 bytes */

__global__ void __launch_bounds__(256, 2) flash_kernel(const unsigned char* __restrict__ mraw)
{
    extern __shared__ __align__(16) float sm[];
    float* Qs  = sm;                 /* [64][68], Qs[d*68+r]  */
    float* Ks  = Qs + 64*FPAD;       /* [64][68], Ks[d*68+c]  */
    float* Vs  = Ks + 64*FPAD;       /* [64][68], Vs[k*68+d]  */
    float* Ps  = Vs + 64*FPAD;       /* [64][68], Ps[r*68+k]  */
    float* Msk = Ps + 64*FPAD;       /* [64] additive mask    */

    const int tid = threadIdx.x;
    const int ty = tid >> 4, tx = tid & 15;
    const int r0 = ty * 4, c0 = tx * 4;
    const int bh = blockIdx.y;       /* 0..95 */
    const int qt = blockIdx.x;       /* 0..15 */
    const int b  = bh / NH;
    const bool mbyte = (g_mask_is_byte != 0);
    const int* mi = (const int*)mraw;

    const float* Qg = g_q + (size_t)(bh*SEQ + qt*64) * HD;
    const float* Kg = g_k + (size_t)bh * SEQ * HD;
    const float* Vg = g_v + (size_t)bh * SEQ * HD;

    /* load Q tile transposed (d-major) */
#pragma unroll
    for (int u = 0; u < 4; u++) {
        int f4 = tid + u * 256;
        int r = f4 >> 4;
        int d = (f4 & 15) << 2;
        float4 v = *(const float4*)(Qg + r*64 + d);
        Qs[(d+0)*FPAD + r] = v.x;
        Qs[(d+1)*FPAD + r] = v.y;
        Qs[(d+2)*FPAD + r] = v.z;
        Qs[(d+3)*FPAD + r] = v.w;
    }

    float O[4][4];
#pragma unroll
    for (int i = 0; i < 4; i++)
#pragma unroll
        for (int j = 0; j < 4; j++) O[i][j] = 0.f;
    float mrow[4] = {-1e30f, -1e30f, -1e30f, -1e30f};
    float lrow[4] = {0.f, 0.f, 0.f, 0.f};

    for (int kt = 0; kt < SEQ/64; kt++) {
        __syncthreads();   /* prev PV done before K/V/P/Msk rewrite */

#pragma unroll
        for (int u = 0; u < 4; u++) {
            int f4 = tid + u * 256;
            int r = f4 >> 4;
            int d = (f4 & 15) << 2;
            float4 kv = *(const float4*)(Kg + (size_t)(kt*64 + r)*64 + d);
            Ks[(d+0)*FPAD + r] = kv.x;
            Ks[(d+1)*FPAD + r] = kv.y;
            Ks[(d+2)*FPAD + r] = kv.z;
            Ks[(d+3)*FPAD + r] = kv.w;
            float4 vv = *(const float4*)(Vg + (size_t)(kt*64 + r)*64 + d);
            *(float4*)&Vs[r*FPAD + d] = vv;
        }
        if (tid < 64) {
            int idx = b*SEQ + kt*64 + tid;
            bool msk = mbyte ? (mraw[idx] != 0) : (mi[idx] != 0);
            Msk[tid] = msk ? -1e30f : 0.f;
        }
        __syncthreads();

        /* S = Q K^T (+mask) */
        float s[4][4];
#pragma unroll
        for (int i = 0; i < 4; i++)
#pragma unroll
            for (int j = 0; j < 4; j++) s[i][j] = 0.f;
#pragma unroll 8
        for (int d = 0; d < 64; d++) {
            float4 q4 = *(const float4*)&Qs[d*FPAD + r0];
            float4 k4 = *(const float4*)&Ks[d*FPAD + c0];
            float qa[4] = {q4.x, q4.y, q4.z, q4.w};
            float ka[4] = {k4.x, k4.y, k4.z, k4.w};
#pragma unroll
            for (int i = 0; i < 4; i++)
#pragma unroll
                for (int j = 0; j < 4; j++)
                    s[i][j] += qa[i] * ka[j];
        }
        float4 mv = *(const float4*)&Msk[c0];
        float mc[4] = {mv.x, mv.y, mv.z, mv.w};
#pragma unroll
        for (int i = 0; i < 4; i++)
#pragma unroll
            for (int j = 0; j < 4; j++) s[i][j] += mc[j];

        /* online softmax */
        float mnew[4], alpha[4];
#pragma unroll
        for (int i = 0; i < 4; i++) {
            float t = fmaxf(fmaxf(s[i][0], s[i][1]), fmaxf(s[i][2], s[i][3]));
#pragma unroll
            for (int off = 1; off < 16; off <<= 1)
                t = fmaxf(t, __shfl_xor_sync(0xffffffffu, t, off));
            mnew[i] = fmaxf(mrow[i], t);
            alpha[i] = __expf(mrow[i] - mnew[i]);
            mrow[i] = mnew[i];
        }
#pragma unroll
        for (int i = 0; i < 4; i++) {
            float p[4];
#pragma unroll
            for (int j = 0; j < 4; j++)
                p[j] = (s[i][j] < -1e29f) ? 0.f : __expf(s[i][j] - mnew[i]);
            *(float4*)&Ps[(r0+i)*FPAD + c0] = make_float4(p[0], p[1], p[2], p[3]);
            float rs = p[0] + p[1] + p[2] + p[3];
#pragma unroll
            for (int off = 1; off < 16; off <<= 1)
                rs += __shfl_xor_sync(0xffffffffu, rs, off);
            lrow[i] = lrow[i] * alpha[i] + rs;
#pragma unroll
            for (int j = 0; j < 4; j++) O[i][j] *= alpha[i];
        }
        __syncthreads();

        /* O += P V */
#pragma unroll 4
        for (int kk = 0; kk < 64; kk++) {
            float4 v4 = *(const float4*)&Vs[kk*FPAD + c0];
#pragma unroll
            for (int i = 0; i < 4; i++) {
                float p = Ps[(r0+i)*FPAD + kk];
                O[i][0] += p * v4.x;
                O[i][1] += p * v4.y;
                O[i][2] += p * v4.z;
                O[i][3] += p * v4.w;
            }
        }
    }

    /* normalize + write to [B,N,C] scratch */
    const int h = bh % NH;
#pragma unroll
    for (int i = 0; i < 4; i++) {
        float inv = 1.f / lrow[i];
        int tok = qt*64 + r0 + i;
        float4 o = make_float4(O[i][0]*inv, O[i][1]*inv, O[i][2]*inv, O[i][3]*inv);
        *(float4*)&g_ao[((size_t)(b*SEQ + tok)) * DIMC + h*HD + c0] = o;
    }
}

/* ---------------- launcher ---------------- */
extern "C" void kernel_launch(void* const* d_in, const int* in_sizes, int n_in,
                              void* d_out, int out_size)
{
    const float* x           = (const float*)d_in[0];
    const unsigned char* msk = (const unsigned char*)d_in[1];
    const float* qkv_w       = (const float*)d_in[2];
    const float* q_bias      = (const float*)d_in[3];
    const float* v_bias      = (const float*)d_in[4];
    const float* proj_w      = (const float*)d_in[5];
    const float* proj_b      = (const float*)d_in[6];
    float* out               = (float*)d_out;

    (void)in_sizes; (void)n_in; (void)out_size;

    detect_mask_kernel<<<1, 256>>>(msk);

    /* QKV: [8192,2304] = x[8192,768] @ qkv_w[2304,768]^T, scatter to g_q/g_k/g_v */
    gemm_nt<0><<<dim3(2304/BN, M_TOT/BM), 256>>>(x, qkv_w, q_bias, v_bias, nullptr);

    cudaFuncSetAttribute(flash_kernel, cudaFuncAttributeMaxDynamicSharedMemorySize,
                         FLASH_SMEM);
    flash_kernel<<<dim3(SEQ/64, BATCH*NH), 256, FLASH_SMEM>>>(msk);

    /* proj: out[8192,768] = g_ao @ proj_w[768,768]^T + proj_b */
    gemm_nt<1><<<dim3(768/BN, M_TOT/BM), 256>>>(nullptr, proj_w, proj_b, nullptr, out);
}

// round 7
// speedup vs baseline: 1.2189x; 1.2189x over previous
#include <cuda_runtime.h>
#include <cuda_bf16.h>
#include <math.h>
#include <cstdint>

#define BATCH 8
#define SEQ   1024
#define DIMC  768
#define NH    12
#define HD    64
#define M_TOT (BATCH*SEQ)     /* 8192 */
#define QK_SCALE 0.125f       /* 64^-0.5 */

/* ---------------- scratch (no cudaMalloc allowed) ---------------- */
__device__ float g_q[BATCH*NH*SEQ*HD];   /* [bh][n][d], q pre-scaled */
__device__ float g_k[BATCH*NH*SEQ*HD];
__device__ float g_v[BATCH*NH*SEQ*HD];
__device__ float g_ao[M_TOT*DIMC];       /* attention out in [B,N,C] */
__device__ int   g_mask_is_byte;

__device__ __forceinline__ uint32_t smem_to_u32(const void* p) {
    uint32_t a;
    asm("{ .reg .u64 t; cvta.to.shared.u64 t, %1; cvt.u32.u64 %0, t; }" : "=r"(a) : "l"(p));
    return a;
}

/* ---------------- baseline-PTX tensor ops (sm_80+; NO sm_103a-gated instrs) ------- */
__device__ __forceinline__ void ldsm_x4(uint32_t& a0, uint32_t& a1, uint32_t& a2,
                                        uint32_t& a3, uint32_t addr) {
    asm volatile("ldmatrix.sync.aligned.m8n8.x4.shared.b16 {%0,%1,%2,%3}, [%4];"
                 : "=r"(a0), "=r"(a1), "=r"(a2), "=r"(a3) : "r"(addr));
}
/* NON-transposed x2: for B stored [n][k] (k-contiguous), delivers lane l ->
   (n = l/4, k = 2*(l%4)+{0,1}) which is exactly the mma.row.col B fragment. */
__device__ __forceinline__ void ldsm_x2(uint32_t& b0, uint32_t& b1, uint32_t addr) {
    asm volatile("ldmatrix.sync.aligned.m8n8.x2.shared.b16 {%0,%1}, [%2];"
                 : "=r"(b0), "=r"(b1) : "r"(addr));
}
__device__ __forceinline__ void mma_bf16(float (&c)[4], const uint32_t (&a)[4],
                                         const uint32_t (&b)[2]) {
    asm volatile("mma.sync.aligned.m16n8k16.row.col.f32.bf16.bf16.f32 "
                 "{%0,%1,%2,%3}, {%4,%5,%6,%7}, {%8,%9}, {%0,%1,%2,%3};"
                 : "+f"(c[0]), "+f"(c[1]), "+f"(c[2]), "+f"(c[3])
                 : "r"(a[0]), "r"(a[1]), "r"(a[2]), "r"(a[3]), "r"(b[0]), "r"(b[1]));
}

/* ---------------- mask dtype sniffing ---------------- */
__global__ void detect_mask_kernel(const unsigned char* __restrict__ m) {
    __shared__ int any;
    if (threadIdx.x == 0) any = 0;
    __syncthreads();
    int loc = 0;
    for (int i = threadIdx.x; i < BATCH*SEQ; i += blockDim.x)
        if ((i & 3) && m[i]) loc = 1;
    if (loc) any = 1;
    __syncthreads();
    if (threadIdx.x == 0) g_mask_is_byte = any;
}

/* ======================================================================
   warp-MMA split-bf16 NT GEMM: C[M,N] = A[M,768] * W[N,768]^T.
   CTA tile 128x128, 8 warps (2x4), warp tile 64x32.
   K chunks of 64 staged in smem as bf16 hi/lo planes (x = hi + lo);
   accumulate hh + hl + lh in fp32 -> ~1e-5 relative error.
   MODE 0: QKV projection -> scatter g_q (+q_bias,*scale)/g_k/g_v(+v_bias)
   MODE 1: output projection (A := g_ao), +proj_b -> Cout.
   ====================================================================== */
#define KC    64                  /* K elems per chunk */
#define NCH   (768/KC)            /* 12 */
#define SSTR  72                  /* halves per smem row (144 B: ldmatrix conflict-free) */
#define TILE_H (128*SSTR)         /* halves per plane */
#define GEMM_SMEM (4*TILE_H*2)    /* 73728 B */

__device__ __forceinline__ void split4(float4 v, uint2& hi, uint2& lo) {
    __nv_bfloat16 h0 = __float2bfloat16(v.x);
    __nv_bfloat16 h1 = __float2bfloat16(v.y);
    __nv_bfloat16 h2 = __float2bfloat16(v.z);
    __nv_bfloat16 h3 = __float2bfloat16(v.w);
    __nv_bfloat16 l0 = __float2bfloat16(v.x - __bfloat162float(h0));
    __nv_bfloat16 l1 = __float2bfloat16(v.y - __bfloat162float(h1));
    __nv_bfloat16 l2 = __float2bfloat16(v.z - __bfloat162float(h2));
    __nv_bfloat16 l3 = __float2bfloat16(v.w - __bfloat162float(h3));
    hi.x = ((uint32_t)__bfloat16_as_ushort(h1) << 16) | __bfloat16_as_ushort(h0);
    hi.y = ((uint32_t)__bfloat16_as_ushort(h3) << 16) | __bfloat16_as_ushort(h2);
    lo.x = ((uint32_t)__bfloat16_as_ushort(l1) << 16) | __bfloat16_as_ushort(l0);
    lo.y = ((uint32_t)__bfloat16_as_ushort(l3) << 16) | __bfloat16_as_ushort(l2);
}

template<int MODE>
__global__ void __launch_bounds__(256) gemm_mma(
    const float* __restrict__ A, const float* __restrict__ W,
    const float* __restrict__ bias0, const float* __restrict__ bias1,
    float* __restrict__ Cout)
{
    extern __shared__ __align__(16) __nv_bfloat16 smb[];
    __nv_bfloat16* Ah = smb;
    __nv_bfloat16* Al = Ah + TILE_H;
    __nv_bfloat16* Bh = Al + TILE_H;
    __nv_bfloat16* Bl = Bh + TILE_H;
    const uint32_t sAh = smem_to_u32(Ah), sAl = smem_to_u32(Al);
    const uint32_t sBh = smem_to_u32(Bh), sBl = smem_to_u32(Bl);

    const int tid = threadIdx.x;
    const int lane = tid & 31;
    const int wid = tid >> 5;
    const int wm = wid >> 2;            /* 0..1 -> m offset 0/64 */
    const int wn = wid & 3;             /* 0..3 -> n offset 0/32/64/96 */
    const int bm = blockIdx.y * 128;
    const int bn = blockIdx.x * 128;

    const float* Ap = (MODE == 1) ? g_ao : A;

    /* ldmatrix lane addressing (element offsets into a plane) */
    const int a_row = lane & 15, a_cb = (lane >> 4) << 3;   /* x4: 16 rows, 2 col-halves */
    const int l2 = lane & 15;
    const int b_row = l2 & 7,  b_cb = ((l2 >> 3) & 1) << 3; /* x2: 8 rows, 2 col-halves */

    float acc[4][4][4];
#pragma unroll
    for (int i = 0; i < 4; i++)
#pragma unroll
        for (int j = 0; j < 4; j++)
#pragma unroll
            for (int t = 0; t < 4; t++) acc[i][j][t] = 0.f;

    for (int kc = 0; kc < NCH; kc++) {
        const int k0 = kc * KC;
        __syncthreads();   /* previous chunk's MMA reads done */
#pragma unroll
        for (int u = 0; u < 8; u++) {
            int f = tid + u * 256;        /* 2048 float4 slots per operand */
            int row = f >> 4;
            int c4 = (f & 15) << 2;
            float4 va = *(const float4*)(Ap + (size_t)(bm + row) * 768 + k0 + c4);
            float4 vb = *(const float4*)(W  + (size_t)(bn + row) * 768 + k0 + c4);
            uint2 h, l;
            int hoff = row * SSTR + c4;
            split4(va, h, l);
            *(uint2*)(Ah + hoff) = h;
            *(uint2*)(Al + hoff) = l;
            split4(vb, h, l);
            *(uint2*)(Bh + hoff) = h;
            *(uint2*)(Bl + hoff) = l;
        }
        __syncthreads();

#pragma unroll
        for (int ks = 0; ks < 4; ks++) {
            const int kh = ks * 16;
            uint32_t af[4][4], bfr[4][2], bl2[4][2];
            /* A hi fragments */
#pragma unroll
            for (int mf = 0; mf < 4; mf++) {
                uint32_t ad = sAh + (uint32_t)(((wm*64 + mf*16 + a_row) * SSTR + kh + a_cb) * 2);
                ldsm_x4(af[mf][0], af[mf][1], af[mf][2], af[mf][3], ad);
            }
            /* B hi fragments */
#pragma unroll
            for (int nf = 0; nf < 4; nf++) {
                uint32_t bd = sBh + (uint32_t)(((wn*32 + nf*8 + b_row) * SSTR + kh + b_cb) * 2);
                ldsm_x2(bfr[nf][0], bfr[nf][1], bd);
            }
            /* pass 1: hi*hi */
#pragma unroll
            for (int mf = 0; mf < 4; mf++)
#pragma unroll
                for (int nf = 0; nf < 4; nf++)
                    mma_bf16(acc[mf][nf], af[mf], bfr[nf]);
            /* B lo fragments; pass 2: hi*lo */
#pragma unroll
            for (int nf = 0; nf < 4; nf++) {
                uint32_t bd = sBl + (uint32_t)(((wn*32 + nf*8 + b_row) * SSTR + kh + b_cb) * 2);
                ldsm_x2(bl2[nf][0], bl2[nf][1], bd);
            }
#pragma unroll
            for (int mf = 0; mf < 4; mf++)
#pragma unroll
                for (int nf = 0; nf < 4; nf++)
                    mma_bf16(acc[mf][nf], af[mf], bl2[nf]);
            /* A lo fragments (reuse regs); pass 3: lo*hi */
#pragma unroll
            for (int mf = 0; mf < 4; mf++) {
                uint32_t ad = sAl + (uint32_t)(((wm*64 + mf*16 + a_row) * SSTR + kh + a_cb) * 2);
                ldsm_x4(af[mf][0], af[mf][1], af[mf][2], af[mf][3], ad);
            }
#pragma unroll
            for (int mf = 0; mf < 4; mf++)
#pragma unroll
                for (int nf = 0; nf < 4; nf++)
                    mma_bf16(acc[mf][nf], af[mf], bfr[nf]);
        }
    }

    /* epilogue: frag (mf,nf): lane holds rows {g, g+8} (g=lane/4),
       cols n = nf*8 + (lane%4)*2 + {0,1} */
    const int gr = lane >> 2;
    const int gc = (lane & 3) << 1;
#pragma unroll
    for (int mf = 0; mf < 4; mf++) {
#pragma unroll
        for (int nf = 0; nf < 4; nf++) {
            int n0 = bn + wn*32 + nf*8 + gc;
#pragma unroll
            for (int half = 0; half < 2; half++) {
                int m = bm + wm*64 + mf*16 + gr + half*8;
                float v0 = acc[mf][nf][half*2 + 0];
                float v1 = acc[mf][nf][half*2 + 1];
                if (MODE == 1) {
                    float2 o = make_float2(v0 + bias0[n0], v1 + bias0[n0+1]);
                    *(float2*)(Cout + (size_t)m * 768 + n0) = o;
                } else {
                    int which = n0 / 768;
                    int nn = n0 % 768;
                    int h = nn >> 6, d0 = nn & 63;
                    int b = m >> 10, tok = m & 1023;
                    float* baseptr = (which == 0) ? g_q : ((which == 1) ? g_k : g_v);
                    if (which == 0) {
                        v0 = (v0 + bias0[nn])   * QK_SCALE;
                        v1 = (v1 + bias0[nn+1]) * QK_SCALE;
                    } else if (which == 2) {
                        v0 += bias1[nn];
                        v1 += bias1[nn+1];
                    }
                    *(float2*)(baseptr + ((size_t)((b*NH + h)*SEQ + tok)) * HD + d0)
                        = make_float2(v0, v1);
                }
            }
        }
    }
}

/* ---------------- flash attention (known-good fp32 version) ---------------- */
#define FPAD 68
#define FLASH_SMEM ((4*64*FPAD + 64) * 4)   /* 69888 bytes */

__global__ void __launch_bounds__(256, 2) flash_kernel(const unsigned char* __restrict__ mraw)
{
    extern __shared__ __align__(16) float sm[];
    float* Qs  = sm;                 /* [64][68], Qs[d*68+r]  */
    float* Ks  = Qs + 64*FPAD;       /* [64][68], Ks[d*68+c]  */
    float* Vs  = Ks + 64*FPAD;       /* [64][68], Vs[k*68+d]  */
    float* Ps  = Vs + 64*FPAD;       /* [64][68], Ps[r*68+k]  */
    float* Msk = Ps + 64*FPAD;       /* [64] additive mask    */

    const int tid = threadIdx.x;
    const int ty = tid >> 4, tx = tid & 15;
    const int r0 = ty * 4, c0 = tx * 4;
    const int bh = blockIdx.y;
    const int qt = blockIdx.x;
    const int b  = bh / NH;
    const bool mbyte = (g_mask_is_byte != 0);
    const int* mi = (const int*)mraw;

    const float* Qg = g_q + (size_t)(bh*SEQ + qt*64) * HD;
    const float* Kg = g_k + (size_t)bh * SEQ * HD;
    const float* Vg = g_v + (size_t)bh * SEQ * HD;

#pragma unroll
    for (int u = 0; u < 4; u++) {
        int f4 = tid + u * 256;
        int r = f4 >> 4;
        int d = (f4 & 15) << 2;
        float4 v = *(const float4*)(Qg + r*64 + d);
        Qs[(d+0)*FPAD + r] = v.x;
        Qs[(d+1)*FPAD + r] = v.y;
        Qs[(d+2)*FPAD + r] = v.z;
        Qs[(d+3)*FPAD + r] = v.w;
    }

    float O[4][4];
#pragma unroll
    for (int i = 0; i < 4; i++)
#pragma unroll
        for (int j = 0; j < 4; j++) O[i][j] = 0.f;
    float mrow[4] = {-1e30f, -1e30f, -1e30f, -1e30f};
    float lrow[4] = {0.f, 0.f, 0.f, 0.f};

    for (int kt = 0; kt < SEQ/64; kt++) {
        __syncthreads();

#pragma unroll
        for (int u = 0; u < 4; u++) {
            int f4 = tid + u * 256;
            int r = f4 >> 4;
            int d = (f4 & 15) << 2;
            float4 kv = *(const float4*)(Kg + (size_t)(kt*64 + r)*64 + d);
            Ks[(d+0)*FPAD + r] = kv.x;
            Ks[(d+1)*FPAD + r] = kv.y;
            Ks[(d+2)*FPAD + r] = kv.z;
            Ks[(d+3)*FPAD + r] = kv.w;
            float4 vv = *(const float4*)(Vg + (size_t)(kt*64 + r)*64 + d);
            *(float4*)&Vs[r*FPAD + d] = vv;
        }
        if (tid < 64) {
            int idx = b*SEQ + kt*64 + tid;
            bool msk = mbyte ? (mraw[idx] != 0) : (mi[idx] != 0);
            Msk[tid] = msk ? -1e30f : 0.f;
        }
        __syncthreads();

        float s[4][4];
#pragma unroll
        for (int i = 0; i < 4; i++)
#pragma unroll
            for (int j = 0; j < 4; j++) s[i][j] = 0.f;
#pragma unroll 8
        for (int d = 0; d < 64; d++) {
            float4 q4 = *(const float4*)&Qs[d*FPAD + r0];
            float4 k4 = *(const float4*)&Ks[d*FPAD + c0];
            float qa[4] = {q4.x, q4.y, q4.z, q4.w};
            float ka[4] = {k4.x, k4.y, k4.z, k4.w};
#pragma unroll
            for (int i = 0; i < 4; i++)
#pragma unroll
                for (int j = 0; j < 4; j++)
                    s[i][j] += qa[i] * ka[j];
        }
        float4 mv = *(const float4*)&Msk[c0];
        float mc[4] = {mv.x, mv.y, mv.z, mv.w};
#pragma unroll
        for (int i = 0; i < 4; i++)
#pragma unroll
            for (int j = 0; j < 4; j++) s[i][j] += mc[j];

        float mnew[4], alpha[4];
#pragma unroll
        for (int i = 0; i < 4; i++) {
            float t = fmaxf(fmaxf(s[i][0], s[i][1]), fmaxf(s[i][2], s[i][3]));
#pragma unroll
            for (int off = 1; off < 16; off <<= 1)
                t = fmaxf(t, __shfl_xor_sync(0xffffffffu, t, off));
            mnew[i] = fmaxf(mrow[i], t);
            alpha[i] = __expf(mrow[i] - mnew[i]);
            mrow[i] = mnew[i];
        }
#pragma unroll
        for (int i = 0; i < 4; i++) {
            float p[4];
#pragma unroll
            for (int j = 0; j < 4; j++)
                p[j] = (s[i][j] < -1e29f) ? 0.f : __expf(s[i][j] - mnew[i]);
            *(float4*)&Ps[(r0+i)*FPAD + c0] = make_float4(p[0], p[1], p[2], p[3]);
            float rs = p[0] + p[1] + p[2] + p[3];
#pragma unroll
            for (int off = 1; off < 16; off <<= 1)
                rs += __shfl_xor_sync(0xffffffffu, rs, off);
            lrow[i] = lrow[i] * alpha[i] + rs;
#pragma unroll
            for (int j = 0; j < 4; j++) O[i][j] *= alpha[i];
        }
        __syncthreads();

#pragma unroll 4
        for (int kk = 0; kk < 64; kk++) {
            float4 v4 = *(const float4*)&Vs[kk*FPAD + c0];
#pragma unroll
            for (int i = 0; i < 4; i++) {
                float p = Ps[(r0+i)*FPAD + kk];
                O[i][0] += p * v4.x;
                O[i][1] += p * v4.y;
                O[i][2] += p * v4.z;
                O[i][3] += p * v4.w;
            }
        }
    }

    const int h = bh % NH;
#pragma unroll
    for (int i = 0; i < 4; i++) {
        float inv = 1.f / lrow[i];
        int tok = qt*64 + r0 + i;
        float4 o = make_float4(O[i][0]*inv, O[i][1]*inv, O[i][2]*inv, O[i][3]*inv);
        *(float4*)&g_ao[((size_t)(b*SEQ + tok)) * DIMC + h*HD + c0] = o;
    }
}

/* ---------------- launcher ---------------- */
extern "C" void kernel_launch(void* const* d_in, const int* in_sizes, int n_in,
                              void* d_out, int out_size)
{
    const float* x           = (const float*)d_in[0];
    const unsigned char* msk = (const unsigned char*)d_in[1];
    const float* qkv_w       = (const float*)d_in[2];
    const float* q_bias      = (const float*)d_in[3];
    const float* v_bias      = (const float*)d_in[4];
    const float* proj_w      = (const float*)d_in[5];
    const float* proj_b      = (const float*)d_in[6];
    float* out               = (float*)d_out;

    (void)in_sizes; (void)n_in; (void)out_size;

    cudaFuncSetAttribute(gemm_mma<0>, cudaFuncAttributeMaxDynamicSharedMemorySize, GEMM_SMEM);
    cudaFuncSetAttribute(gemm_mma<1>, cudaFuncAttributeMaxDynamicSharedMemorySize, GEMM_SMEM);
    cudaFuncSetAttribute(flash_kernel, cudaFuncAttributeMaxDynamicSharedMemorySize, FLASH_SMEM);

    detect_mask_kernel<<<1, 256>>>(msk);

    /* QKV: [8192,2304] = x @ qkv_w^T -> scatter g_q/g_k/g_v */
    gemm_mma<0><<<dim3(2304/128, M_TOT/128), 256, GEMM_SMEM>>>(x, qkv_w, q_bias, v_bias, nullptr);

    flash_kernel<<<dim3(SEQ/64, BATCH*NH), 256, FLASH_SMEM>>>(msk);

    /* proj: out = g_ao @ proj_w^T + proj_b */
    gemm_mma<1><<<dim3(768/128, M_TOT/128), 256, GEMM_SMEM>>>(nullptr, proj_w, proj_b, nullptr, out);
}

// round 8
// speedup vs baseline: 2.4965x; 2.0481x over previous
#include <cuda_runtime.h>
#include <cuda_bf16.h>
#include <math.h>
#include <cstdint>

#define BATCH 8
#define SEQ   1024
#define DIMC  768
#define NH    12
#define HD    64
#define M_TOT (BATCH*SEQ)     /* 8192 */
#define QK_SCALE 0.125f       /* 64^-0.5 */
#define BH    (BATCH*NH)      /* 96 */

typedef __nv_bfloat16 bf16;

/* ---------------- scratch (no cudaMalloc allowed) ---------------- */
__device__ bf16 g_xh[M_TOT*DIMC],  g_xl[M_TOT*DIMC];      /* x split          */
__device__ bf16 g_wqh[3*DIMC*DIMC], g_wql[3*DIMC*DIMC];   /* qkv_w split      */
__device__ bf16 g_wph[DIMC*DIMC],  g_wpl[DIMC*DIMC];      /* proj_w split     */
__device__ bf16 g_qh[BH*SEQ*HD], g_ql[BH*SEQ*HD];         /* q (scaled+bias)  */
__device__ bf16 g_kh[BH*SEQ*HD], g_kl[BH*SEQ*HD];
__device__ bf16 g_vh[BH*SEQ*HD], g_vl[BH*SEQ*HD];
__device__ bf16 g_aoh[M_TOT*DIMC], g_aol[M_TOT*DIMC];     /* attn out split   */
__device__ int  g_mask_is_byte;

__device__ __forceinline__ uint32_t smem_to_u32(const void* p) {
    uint32_t a;
    asm("{ .reg .u64 t; cvta.to.shared.u64 t, %1; cvt.u32.u64 %0, t; }" : "=r"(a) : "l"(p));
    return a;
}

/* ---------------- baseline-PTX tensor ops ---------------- */
__device__ __forceinline__ void ldsm_x4(uint32_t& a0, uint32_t& a1, uint32_t& a2,
                                        uint32_t& a3, uint32_t addr) {
    asm volatile("ldmatrix.sync.aligned.m8n8.x4.shared.b16 {%0,%1,%2,%3}, [%4];"
                 : "=r"(a0), "=r"(a1), "=r"(a2), "=r"(a3) : "r"(addr));
}
__device__ __forceinline__ void ldsm_x4_t(uint32_t& a0, uint32_t& a1, uint32_t& a2,
                                          uint32_t& a3, uint32_t addr) {
    asm volatile("ldmatrix.sync.aligned.m8n8.x4.trans.shared.b16 {%0,%1,%2,%3}, [%4];"
                 : "=r"(a0), "=r"(a1), "=r"(a2), "=r"(a3) : "r"(addr));
}
__device__ __forceinline__ void mma_bf16(float (&c)[4], const uint32_t (&a)[4],
                                         const uint32_t (&b)[2]) {
    asm volatile("mma.sync.aligned.m16n8k16.row.col.f32.bf16.bf16.f32 "
                 "{%0,%1,%2,%3}, {%4,%5,%6,%7}, {%8,%9}, {%0,%1,%2,%3};"
                 : "+f"(c[0]), "+f"(c[1]), "+f"(c[2]), "+f"(c[3])
                 : "r"(a[0]), "r"(a[1]), "r"(a[2]), "r"(a[3]), "r"(b[0]), "r"(b[1]));
}

/* split a pair of fp32 into packed bf16 hi-pair / lo-pair (low half = first) */
__device__ __forceinline__ void split2(float a, float b, uint32_t& hi, uint32_t& lo) {
    bf16 ha = __float2bfloat16(a), hb = __float2bfloat16(b);
    bf16 la = __float2bfloat16(a - __bfloat162float(ha));
    bf16 lb = __float2bfloat16(b - __bfloat162float(hb));
    hi = ((uint32_t)__bfloat16_as_ushort(hb) << 16) | __bfloat16_as_ushort(ha);
    lo = ((uint32_t)__bfloat16_as_ushort(lb) << 16) | __bfloat16_as_ushort(la);
}

/* ---------------- preprocessing: fp32 -> bf16 hi/lo planes ---------------- */
__global__ void split_kernel(const float* __restrict__ src, bf16* __restrict__ hi,
                             bf16* __restrict__ lo, int n4) {
    int i = blockIdx.x * blockDim.x + threadIdx.x;
    int stride = gridDim.x * blockDim.x;
    for (; i < n4; i += stride) {
        float4 v = ((const float4*)src)[i];
        uint32_t h0, l0, h1, l1;
        split2(v.x, v.y, h0, l0);
        split2(v.z, v.w, h1, l1);
        ((uint2*)hi)[i] = make_uint2(h0, h1);
        ((uint2*)lo)[i] = make_uint2(l0, l1);
    }
}

/* ---------------- mask dtype sniffing ---------------- */
__global__ void detect_mask_kernel(const unsigned char* __restrict__ m) {
    __shared__ int any;
    if (threadIdx.x == 0) any = 0;
    __syncthreads();
    int loc = 0;
    for (int i = threadIdx.x; i < BATCH*SEQ; i += blockDim.x)
        if ((i & 3) && m[i]) loc = 1;
    if (loc) any = 1;
    __syncthreads();
    if (threadIdx.x == 0) g_mask_is_byte = any;
}

/* ======================================================================
   warp-MMA split-bf16 NT GEMM on precomputed planes.
   C[M,N] = (Ah+Al)[M,768] * (Bh+Bl)[N,768]^T, 3 passes hh+hl+lh.
   CTA 128x128, 8 warps (2x4), warp tile 64x32. 2 CTAs/SM.
   ====================================================================== */
#define KC    64
#define NCH   (768/KC)
#define SSTR  72
#define TILE_H (128*SSTR)
#define GEMM_SMEM (4*TILE_H*2)    /* 73728 B */

template<int MODE>
__global__ void __launch_bounds__(256, 2) gemm_mma(
    const bf16* __restrict__ Ahg, const bf16* __restrict__ Alg,
    const bf16* __restrict__ Bhg, const bf16* __restrict__ Blg,
    const float* __restrict__ bias0, const float* __restrict__ bias1,
    float* __restrict__ Cout)
{
    extern __shared__ __align__(16) bf16 smb[];
    bf16* Ah = smb;
    bf16* Al = Ah + TILE_H;
    bf16* Bh = Al + TILE_H;
    bf16* Bl = Bh + TILE_H;
    const uint32_t sAh = smem_to_u32(Ah), sAl = smem_to_u32(Al);
    const uint32_t sBh = smem_to_u32(Bh), sBl = smem_to_u32(Bl);

    const int tid = threadIdx.x;
    const int lane = tid & 31;
    const int wid = tid >> 5;
    const int wm = wid >> 2, wn = wid & 3;
    const int bm = blockIdx.y * 128, bn = blockIdx.x * 128;

    const int a_row = lane & 15, a_cb = (lane >> 4) << 3;
    const int l2 = lane & 15;
    const int b_row = l2 & 7,  b_cb = ((l2 >> 3) & 1) << 3;

    float acc[4][4][4];
#pragma unroll
    for (int i = 0; i < 4; i++)
#pragma unroll
        for (int j = 0; j < 4; j++)
#pragma unroll
            for (int t = 0; t < 4; t++) acc[i][j][t] = 0.f;

    for (int kc = 0; kc < NCH; kc++) {
        const int k0 = kc * KC;
        __syncthreads();
        /* copy bf16 planes: 1024 uint4 slots per plane */
#pragma unroll
        for (int u = 0; u < 4; u++) {
            int idx = tid + u * 256;
            int row = idx >> 3;
            int c8 = (idx & 7) << 3;
            int soff = row * SSTR + c8;
            size_t ga = (size_t)(bm + row) * 768 + k0 + c8;
            size_t gb = (size_t)(bn + row) * 768 + k0 + c8;
            *(uint4*)(Ah + soff) = *(const uint4*)(Ahg + ga);
            *(uint4*)(Al + soff) = *(const uint4*)(Alg + ga);
            *(uint4*)(Bh + soff) = *(const uint4*)(Bhg + gb);
            *(uint4*)(Bl + soff) = *(const uint4*)(Blg + gb);
        }
        __syncthreads();

#pragma unroll
        for (int ks = 0; ks < 4; ks++) {
            const int kh = ks * 16;
            uint32_t af[4][4], bfr[4][2], bl2[4][2];
#pragma unroll
            for (int mf = 0; mf < 4; mf++) {
                uint32_t ad = sAh + (uint32_t)(((wm*64 + mf*16 + a_row) * SSTR + kh + a_cb) * 2);
                ldsm_x4(af[mf][0], af[mf][1], af[mf][2], af[mf][3], ad);
            }
#pragma unroll
            for (int nf = 0; nf < 4; nf++) {
                uint32_t bd = sBh + (uint32_t)(((wn*32 + nf*8 + b_row) * SSTR + kh + b_cb) * 2);
                asm volatile("ldmatrix.sync.aligned.m8n8.x2.shared.b16 {%0,%1}, [%2];"
                             : "=r"(bfr[nf][0]), "=r"(bfr[nf][1]) : "r"(bd));
            }
#pragma unroll
            for (int mf = 0; mf < 4; mf++)
#pragma unroll
                for (int nf = 0; nf < 4; nf++)
                    mma_bf16(acc[mf][nf], af[mf], bfr[nf]);
#pragma unroll
            for (int nf = 0; nf < 4; nf++) {
                uint32_t bd = sBl + (uint32_t)(((wn*32 + nf*8 + b_row) * SSTR + kh + b_cb) * 2);
                asm volatile("ldmatrix.sync.aligned.m8n8.x2.shared.b16 {%0,%1}, [%2];"
                             : "=r"(bl2[nf][0]), "=r"(bl2[nf][1]) : "r"(bd));
            }
#pragma unroll
            for (int mf = 0; mf < 4; mf++)
#pragma unroll
                for (int nf = 0; nf < 4; nf++)
                    mma_bf16(acc[mf][nf], af[mf], bl2[nf]);
#pragma unroll
            for (int mf = 0; mf < 4; mf++) {
                uint32_t ad = sAl + (uint32_t)(((wm*64 + mf*16 + a_row) * SSTR + kh + a_cb) * 2);
                ldsm_x4(af[mf][0], af[mf][1], af[mf][2], af[mf][3], ad);
            }
#pragma unroll
            for (int mf = 0; mf < 4; mf++)
#pragma unroll
                for (int nf = 0; nf < 4; nf++)
                    mma_bf16(acc[mf][nf], af[mf], bfr[nf]);
        }
    }

    const int gr = lane >> 2;
    const int gc = (lane & 3) << 1;
#pragma unroll
    for (int mf = 0; mf < 4; mf++) {
#pragma unroll
        for (int nf = 0; nf < 4; nf++) {
            int n0 = bn + wn*32 + nf*8 + gc;
#pragma unroll
            for (int half = 0; half < 2; half++) {
                int m = bm + wm*64 + mf*16 + gr + half*8;
                float v0 = acc[mf][nf][half*2 + 0];
                float v1 = acc[mf][nf][half*2 + 1];
                if (MODE == 1) {
                    float2 o = make_float2(v0 + bias0[n0], v1 + bias0[n0+1]);
                    *(float2*)(Cout + (size_t)m * 768 + n0) = o;
                } else {
                    int which = n0 / 768;
                    int nn = n0 % 768;
                    int h = nn >> 6, d0 = nn & 63;
                    int b = m >> 10, tok = m & 1023;
                    if (which == 0) {
                        v0 = (v0 + bias0[nn])   * QK_SCALE;
                        v1 = (v1 + bias0[nn+1]) * QK_SCALE;
                    } else if (which == 2) {
                        v0 += bias1[nn];
                        v1 += bias1[nn+1];
                    }
                    uint32_t hp, lp;
                    split2(v0, v1, hp, lp);
                    size_t off = ((size_t)((b*NH + h)*SEQ + tok)) * HD + d0;
                    bf16* ph = (which == 0) ? g_qh : ((which == 1) ? g_kh : g_vh);
                    bf16* pl = (which == 0) ? g_ql : ((which == 1) ? g_kl : g_vl);
                    *(uint32_t*)(ph + off) = hp;
                    *(uint32_t*)(pl + off) = lp;
                }
            }
        }
    }
}

/* ======================================================================
   flash attention with warp MMA (split-bf16 3-pass on both GEMMs).
   CTA = 128 q-rows of one (b,h); 8 warps, each owns 16 q-rows x 64 keys.
   K tiles of 64 keys. Softmax fully warp-local; P repacked in registers.
   ====================================================================== */
#define FSTR 72
#define FLASH_STAGE_H (256*FSTR)                 /* union: Q(2x128) / KV(4x64) rows */
#define FLASH_SMEM (FLASH_STAGE_H*2 + 256)       /* 37120 B */

__global__ void __launch_bounds__(256, 1) flash_mma(const unsigned char* __restrict__ mraw)
{
    extern __shared__ __align__(16) bf16 fsm[];
    bf16* stage = fsm;
    float* Msk = (float*)(fsm + FLASH_STAGE_H);

    const int tid = threadIdx.x;
    const int lane = tid & 31;
    const int wid = tid >> 5;               /* 0..7: owns q rows wid*16.. */
    const int bh = blockIdx.y;
    const int qt = blockIdx.x;              /* 0..7: 128-row q tile */
    const int b = bh / NH, h = bh % NH;
    const bool mbyte = (g_mask_is_byte != 0);
    const int* mi = (const int*)mraw;

    const uint32_t sstage = smem_to_u32(stage);
    /* stage layouts */
    bf16* Qh_s = stage;                     /* [128][FSTR] */
    bf16* Ql_s = stage + 128*FSTR;
    bf16* Kh_s = stage;                     /* [64][FSTR] each */
    bf16* Kl_s = stage + 64*FSTR;
    bf16* Vh_s = stage + 128*FSTR;
    bf16* Vl_s = stage + 192*FSTR;
    const uint32_t sKh = smem_to_u32(Kh_s), sKl = smem_to_u32(Kl_s);
    const uint32_t sVh = smem_to_u32(Vh_s), sVl = smem_to_u32(Vl_s);

    const size_t qbase = ((size_t)bh*SEQ + qt*128) * HD;
    const size_t kvbase = (size_t)bh*SEQ*HD;

    /* ---- stage Q and load Q fragments (once) ---- */
#pragma unroll
    for (int u = 0; u < 4; u++) {
        int idx = tid + u * 256;            /* 1024 slots/plane */
        int row = idx >> 3;
        int c8 = (idx & 7) << 3;
        *(uint4*)(Qh_s + row*FSTR + c8) = *(const uint4*)(g_qh + qbase + row*64 + c8);
        *(uint4*)(Ql_s + row*FSTR + c8) = *(const uint4*)(g_ql + qbase + row*64 + c8);
    }
    __syncthreads();

    uint32_t qh[4][4], ql[4][4];
    {
        int row = wid*16 + (lane & 15);
        int cb = (lane >> 4) << 3;
#pragma unroll
        for (int ks = 0; ks < 4; ks++) {
            uint32_t off = (uint32_t)((row*FSTR + ks*16 + cb) * 2);
            ldsm_x4(qh[ks][0], qh[ks][1], qh[ks][2], qh[ks][3], sstage + off);
            ldsm_x4(ql[ks][0], ql[ks][1], ql[ks][2], ql[ks][3],
                    sstage + (uint32_t)(128*FSTR*2) + off);
        }
    }

    float o[8][4];
#pragma unroll
    for (int i = 0; i < 8; i++)
#pragma unroll
        for (int t = 0; t < 4; t++) o[i][t] = 0.f;
    float m0 = -1e30f, m1 = -1e30f, l0 = 0.f, l1 = 0.f;

    const int gr = lane >> 2;
    const int gc = (lane & 3) << 1;

    for (int kt = 0; kt < SEQ/64; kt++) {
        __syncthreads();                     /* Q frags done / prev tile consumed */
        /* ---- stage K/V tile (64 rows x 4 planes) ---- */
#pragma unroll
        for (int u = 0; u < 2; u++) {
            int idx = tid + u * 256;         /* 512 slots/plane */
            int row = idx >> 3;
            int c8 = (idx & 7) << 3;
            size_t g = kvbase + (size_t)(kt*64 + row)*64 + c8;
            int soff = row*FSTR + c8;
            *(uint4*)(Kh_s + soff) = *(const uint4*)(g_kh + g);
            *(uint4*)(Kl_s + soff) = *(const uint4*)(g_kl + g);
            *(uint4*)(Vh_s + soff) = *(const uint4*)(g_vh + g);
            *(uint4*)(Vl_s + soff) = *(const uint4*)(g_vl + g);
        }
        if (tid < 64) {
            int idx = b*SEQ + kt*64 + tid;
            bool msk = mbyte ? (mraw[idx] != 0) : (mi[idx] != 0);
            Msk[tid] = msk ? -1e30f : 0.f;
        }
        __syncthreads();

        /* ---- S = (Qh+Ql)(Kh+Kl)^T, 3 passes ---- */
        float s4[8][4];
#pragma unroll
        for (int i = 0; i < 8; i++)
#pragma unroll
            for (int t = 0; t < 4; t++) s4[i][t] = 0.f;

        {
            int krow = lane & 15;
            int kcb = (lane >> 4) << 3;
#pragma unroll
            for (int ks = 0; ks < 4; ks++) {
                uint32_t kbh[8][2], kbl[8][2];
#pragma unroll
                for (int np = 0; np < 4; np++) {
                    uint32_t off = (uint32_t)(((np*16 + krow)*FSTR + ks*16 + kcb) * 2);
                    uint32_t r0, r1, r2, r3;
                    ldsm_x4(r0, r1, r2, r3, sKh + off);
                    kbh[2*np][0] = r0; kbh[2*np][1] = r2;
                    kbh[2*np+1][0] = r1; kbh[2*np+1][1] = r3;
                    ldsm_x4(r0, r1, r2, r3, sKl + off);
                    kbl[2*np][0] = r0; kbl[2*np][1] = r2;
                    kbl[2*np+1][0] = r1; kbl[2*np+1][1] = r3;
                }
#pragma unroll
                for (int nf = 0; nf < 8; nf++) mma_bf16(s4[nf], qh[ks], kbh[nf]);
#pragma unroll
                for (int nf = 0; nf < 8; nf++) mma_bf16(s4[nf], qh[ks], kbl[nf]);
#pragma unroll
                for (int nf = 0; nf < 8; nf++) mma_bf16(s4[nf], ql[ks], kbh[nf]);
            }
        }

        /* ---- mask + online softmax (rows gr, gr+8 per lane) ---- */
        float tm0 = -1e30f, tm1 = -1e30f;
#pragma unroll
        for (int nf = 0; nf < 8; nf++) {
            float2 mk = *(float2*)(Msk + nf*8 + gc);
            s4[nf][0] += mk.x; s4[nf][1] += mk.y;
            s4[nf][2] += mk.x; s4[nf][3] += mk.y;
            tm0 = fmaxf(tm0, fmaxf(s4[nf][0], s4[nf][1]));
            tm1 = fmaxf(tm1, fmaxf(s4[nf][2], s4[nf][3]));
        }
        tm0 = fmaxf(tm0, __shfl_xor_sync(0xffffffffu, tm0, 1));
        tm0 = fmaxf(tm0, __shfl_xor_sync(0xffffffffu, tm0, 2));
        tm1 = fmaxf(tm1, __shfl_xor_sync(0xffffffffu, tm1, 1));
        tm1 = fmaxf(tm1, __shfl_xor_sync(0xffffffffu, tm1, 2));
        float mn0 = fmaxf(m0, tm0), mn1 = fmaxf(m1, tm1);
        float al0 = __expf(m0 - mn0), al1 = __expf(m1 - mn1);
        m0 = mn0; m1 = mn1;
        float ls0 = 0.f, ls1 = 0.f;
#pragma unroll
        for (int nf = 0; nf < 8; nf++) {
            s4[nf][0] = __expf(s4[nf][0] - mn0);
            s4[nf][1] = __expf(s4[nf][1] - mn0);
            s4[nf][2] = __expf(s4[nf][2] - mn1);
            s4[nf][3] = __expf(s4[nf][3] - mn1);
            ls0 += s4[nf][0] + s4[nf][1];
            ls1 += s4[nf][2] + s4[nf][3];
        }
        ls0 += __shfl_xor_sync(0xffffffffu, ls0, 1);
        ls0 += __shfl_xor_sync(0xffffffffu, ls0, 2);
        ls1 += __shfl_xor_sync(0xffffffffu, ls1, 1);
        ls1 += __shfl_xor_sync(0xffffffffu, ls1, 2);
        l0 = l0 * al0 + ls0;
        l1 = l1 * al1 + ls1;
#pragma unroll
        for (int nf = 0; nf < 8; nf++) {
            o[nf][0] *= al0; o[nf][1] *= al0;
            o[nf][2] *= al1; o[nf][3] *= al1;
        }

        /* ---- O += (Ph+Pl)(Vh+Vl), 3 passes; P packed from registers ---- */
        {
            int vrow = lane & 15;
            int vcb = (lane >> 4) << 3;
#pragma unroll
            for (int ksv = 0; ksv < 4; ksv++) {
                uint32_t ph[4], pl[4];
                split2(s4[2*ksv][0],   s4[2*ksv][1],   ph[0], pl[0]);
                split2(s4[2*ksv][2],   s4[2*ksv][3],   ph[1], pl[1]);
                split2(s4[2*ksv+1][0], s4[2*ksv+1][1], ph[2], pl[2]);
                split2(s4[2*ksv+1][2], s4[2*ksv+1][3], ph[3], pl[3]);
#pragma unroll
                for (int np = 0; np < 4; np++) {
                    uint32_t off = (uint32_t)(((ksv*16 + vrow)*FSTR + np*16 + vcb) * 2);
                    uint32_t vh0[2], vh1[2], vl0[2], vl1[2];
                    uint32_t r0, r1, r2, r3;
                    ldsm_x4_t(r0, r1, r2, r3, sVh + off);
                    vh0[0] = r0; vh0[1] = r1; vh1[0] = r2; vh1[1] = r3;
                    ldsm_x4_t(r0, r1, r2, r3, sVl + off);
                    vl0[0] = r0; vl0[1] = r1; vl1[0] = r2; vl1[1] = r3;
                    mma_bf16(o[2*np],   ph, vh0);
                    mma_bf16(o[2*np+1], ph, vh1);
                    mma_bf16(o[2*np],   ph, vl0);
                    mma_bf16(o[2*np+1], ph, vl1);
                    mma_bf16(o[2*np],   pl, vh0);
                    mma_bf16(o[2*np+1], pl, vh1);
                }
            }
        }
    }

    /* ---- finalize: O /= l, write split planes [tok][C] ---- */
    float inv0 = 1.f / l0, inv1 = 1.f / l1;
    int tok0 = qt*128 + wid*16 + gr;
    size_t r0g = ((size_t)(b*SEQ + tok0)) * DIMC + h*HD;
    size_t r1g = r0g + 8*DIMC;
#pragma unroll
    for (int nf = 0; nf < 8; nf++) {
        int d = nf*8 + gc;
        uint32_t hp, lp;
        split2(o[nf][0]*inv0, o[nf][1]*inv0, hp, lp);
        *(uint32_t*)(g_aoh + r0g + d) = hp;
        *(uint32_t*)(g_aol + r0g + d) = lp;
        split2(o[nf][2]*inv1, o[nf][3]*inv1, hp, lp);
        *(uint32_t*)(g_aoh + r1g + d) = hp;
        *(uint32_t*)(g_aol + r1g + d) = lp;
    }
}

/* ---------------- launcher ---------------- */
extern "C" void kernel_launch(void* const* d_in, const int* in_sizes, int n_in,
                              void* d_out, int out_size)
{
    const float* x           = (const float*)d_in[0];
    const unsigned char* msk = (const unsigned char*)d_in[1];
    const float* qkv_w       = (const float*)d_in[2];
    const float* q_bias      = (const float*)d_in[3];
    const float* v_bias      = (const float*)d_in[4];
    const float* proj_w      = (const float*)d_in[5];
    const float* proj_b      = (const float*)d_in[6];
    float* out               = (float*)d_out;

    (void)in_sizes; (void)n_in; (void)out_size;

    cudaFuncSetAttribute(gemm_mma<0>, cudaFuncAttributeMaxDynamicSharedMemorySize, GEMM_SMEM);
    cudaFuncSetAttribute(gemm_mma<1>, cudaFuncAttributeMaxDynamicSharedMemorySize, GEMM_SMEM);
    cudaFuncSetAttribute(flash_mma, cudaFuncAttributeMaxDynamicSharedMemorySize, FLASH_SMEM);

    detect_mask_kernel<<<1, 256>>>(msk);

    bf16 *xh, *xl, *wqh, *wql, *wph, *wpl;
    cudaGetSymbolAddress((void**)&xh,  g_xh);  cudaGetSymbolAddress((void**)&xl,  g_xl);
    cudaGetSymbolAddress((void**)&wqh, g_wqh); cudaGetSymbolAddress((void**)&wql, g_wql);
    cudaGetSymbolAddress((void**)&wph, g_wph); cudaGetSymbolAddress((void**)&wpl, g_wpl);

    split_kernel<<<1024, 256>>>(x,      xh,  xl,  M_TOT*DIMC/4);
    split_kernel<<<512,  256>>>(qkv_w,  wqh, wql, 3*DIMC*DIMC/4);
    split_kernel<<<256,  256>>>(proj_w, wph, wpl, DIMC*DIMC/4);

    /* QKV: [8192,2304] -> split q/k/v planes */
    gemm_mma<0><<<dim3(2304/128, M_TOT/128), 256, GEMM_SMEM>>>(
        xh, xl, wqh, wql, q_bias, v_bias, nullptr);

    flash_mma<<<dim3(SEQ/128, BH), 256, FLASH_SMEM>>>(msk);

    bf16 *aoh, *aol;
    cudaGetSymbolAddress((void**)&aoh, g_aoh); cudaGetSymbolAddress((void**)&aol, g_aol);
    /* proj: out = (aoh+aol) @ (wph+wpl)^T + proj_b */
    gemm_mma<1><<<dim3(768/128, M_TOT/128), 256, GEMM_SMEM>>>(
        aoh, aol, wph, wpl, proj_b, nullptr, out);
}

// round 10
// speedup vs baseline: 2.6933x; 1.0788x over previous
#include <cuda_runtime.h>
#include <cuda_bf16.h>
#include <math.h>
#include <cstdint>

#define BATCH 8
#define SEQ   1024
#define DIMC  768
#define NH    12
#define HD    64
#define M_TOT (BATCH*SEQ)     /* 8192 */
#define QK_SCALE 0.125f
#define BH    (BATCH*NH)      /* 96 */

typedef __nv_bfloat16 bf16;

/* ---------------- scratch (no cudaMalloc allowed) ---------------- */
__device__ bf16 g_xh[M_TOT*DIMC],  g_xl[M_TOT*DIMC];
__device__ bf16 g_wqh[3*DIMC*DIMC], g_wql[3*DIMC*DIMC];
__device__ bf16 g_wph[DIMC*DIMC],  g_wpl[DIMC*DIMC];
__device__ bf16 g_qh[BH*SEQ*HD], g_ql[BH*SEQ*HD];
__device__ bf16 g_kh[BH*SEQ*HD], g_kl[BH*SEQ*HD];
__device__ bf16 g_vh[BH*SEQ*HD], g_vl[BH*SEQ*HD];
__device__ bf16 g_aoh[M_TOT*DIMC], g_aol[M_TOT*DIMC];
__device__ float g_maskf[BATCH*SEQ];
__device__ int  g_mask_is_byte;

__device__ __forceinline__ uint32_t smem_to_u32(const void* p) {
    uint32_t a;
    asm("{ .reg .u64 t; cvta.to.shared.u64 t, %1; cvt.u32.u64 %0, t; }" : "=r"(a) : "l"(p));
    return a;
}

/* ---------------- baseline-PTX tensor / async ops ---------------- */
__device__ __forceinline__ void ldsm_x4(uint32_t& a0, uint32_t& a1, uint32_t& a2,
                                        uint32_t& a3, uint32_t addr) {
    asm volatile("ldmatrix.sync.aligned.m8n8.x4.shared.b16 {%0,%1,%2,%3}, [%4];"
                 : "=r"(a0), "=r"(a1), "=r"(a2), "=r"(a3) : "r"(addr));
}
__device__ __forceinline__ void ldsm_x4_t(uint32_t& a0, uint32_t& a1, uint32_t& a2,
                                          uint32_t& a3, uint32_t addr) {
    asm volatile("ldmatrix.sync.aligned.m8n8.x4.trans.shared.b16 {%0,%1,%2,%3}, [%4];"
                 : "=r"(a0), "=r"(a1), "=r"(a2), "=r"(a3) : "r"(addr));
}
__device__ __forceinline__ void mma_bf16(float (&c)[4], const uint32_t (&a)[4],
                                         const uint32_t (&b)[2]) {
    asm volatile("mma.sync.aligned.m16n8k16.row.col.f32.bf16.bf16.f32 "
                 "{%0,%1,%2,%3}, {%4,%5,%6,%7}, {%8,%9}, {%0,%1,%2,%3};"
                 : "+f"(c[0]), "+f"(c[1]), "+f"(c[2]), "+f"(c[3])
                 : "r"(a[0]), "r"(a[1]), "r"(a[2]), "r"(a[3]), "r"(b[0]), "r"(b[1]));
}
#define CP16(dst, src) \
    asm volatile("cp.async.cg.shared.global [%0], [%1], 16;" :: "r"(dst), "l"(src))
#define CP_COMMIT() asm volatile("cp.async.commit_group;" ::: "memory")
#define CP_WAIT1()  asm volatile("cp.async.wait_group 1;" ::: "memory")
#define CP_WAIT0()  asm volatile("cp.async.wait_group 0;" ::: "memory")

__device__ __forceinline__ void split2(float a, float b, uint32_t& hi, uint32_t& lo) {
    bf16 ha = __float2bfloat16(a), hb = __float2bfloat16(b);
    bf16 la = __float2bfloat16(a - __bfloat162float(ha));
    bf16 lb = __float2bfloat16(b - __bfloat162float(hb));
    hi = ((uint32_t)__bfloat16_as_ushort(hb) << 16) | __bfloat16_as_ushort(ha);
    lo = ((uint32_t)__bfloat16_as_ushort(lb) << 16) | __bfloat16_as_ushort(la);
}

/* ---------------- preprocessing kernels ---------------- */
__global__ void split_kernel(const float* __restrict__ src, bf16* __restrict__ hi,
                             bf16* __restrict__ lo, int n4) {
    int i = blockIdx.x * blockDim.x + threadIdx.x;
    int stride = gridDim.x * blockDim.x;
    for (; i < n4; i += stride) {
        float4 v = ((const float4*)src)[i];
        uint32_t h0, l0, h1, l1;
        split2(v.x, v.y, h0, l0);
        split2(v.z, v.w, h1, l1);
        ((uint2*)hi)[i] = make_uint2(h0, h1);
        ((uint2*)lo)[i] = make_uint2(l0, l1);
    }
}
__global__ void detect_mask_kernel(const unsigned char* __restrict__ m) {
    __shared__ int any;
    if (threadIdx.x == 0) any = 0;
    __syncthreads();
    int loc = 0;
    for (int i = threadIdx.x; i < BATCH*SEQ; i += blockDim.x)
        if ((i & 3) && m[i]) loc = 1;
    if (loc) any = 1;
    __syncthreads();
    if (threadIdx.x == 0) g_mask_is_byte = any;
}
__global__ void maskf_kernel(const unsigned char* __restrict__ m) {
    int i = blockIdx.x * blockDim.x + threadIdx.x;
    if (i < BATCH*SEQ) {
        bool msk = g_mask_is_byte ? (m[i] != 0) : (((const int*)m)[i] != 0);
        g_maskf[i] = msk ? -1e30f : 0.f;
    }
}

/* ======================================================================
   cp.async double-buffered warp-MMA split-bf16 NT GEMM.
   CTA 128x128, 8 warps (2x4), warp 64x32. KC=32, 2 stages. 2 CTAs/SM.
   ====================================================================== */
#define KC2    32
#define NCH2   (768/KC2)          /* 24 */
#define GS     40                 /* halves per row (80 B, ldmatrix-safe) */
#define PLANE_B (128*GS*2)        /* 10240 B */
#define STAGE_B (4*PLANE_B)       /* 40960 B */
#define GEMM_SMEM (2*STAGE_B)     /* 81920 B */

template<int MODE>
__global__ void __launch_bounds__(256, 2) gemm_mma(
    const bf16* __restrict__ Ahg, const bf16* __restrict__ Alg,
    const bf16* __restrict__ Bhg, const bf16* __restrict__ Blg,
    const float* __restrict__ bias0, const float* __restrict__ bias1,
    float* __restrict__ Cout)
{
    extern __shared__ __align__(16) bf16 smb[];
    const uint32_t sb = smem_to_u32(smb);

    const int tid = threadIdx.x;
    const int lane = tid & 31;
    const int wid = tid >> 5;
    const int wm = wid >> 2, wn = wid & 3;
    const int bm = blockIdx.y * 128, bn = blockIdx.x * 128;

    const int a_row = lane & 15, a_cb = (lane >> 4) << 3;
    const int l2 = lane & 15;
    const int b_row = l2 & 7,  b_cb = ((l2 >> 3) & 1) << 3;

    float acc[4][4][4];
#pragma unroll
    for (int i = 0; i < 4; i++)
#pragma unroll
        for (int j = 0; j < 4; j++)
#pragma unroll
            for (int t = 0; t < 4; t++) acc[i][j][t] = 0.f;

    /* issue one stage's cp.asyncs (8 per thread).
       Each plane: 128 rows x 32 halves = 4 uint4-slots/row x 128 = 512 slots. */
    auto issue = [&](int kc) {
        const int k0 = kc * KC2;
        const uint32_t st = sb + (uint32_t)((kc & 1) * STAGE_B);
#pragma unroll
        for (int u = 0; u < 8; u++) {
            int idx = tid + u * 256;
            int plane = idx >> 9;
            int rem = idx & 511;
            int row = rem >> 2;
            int c8 = (rem & 3) << 3;
            const bf16* gp = (plane == 0) ? Ahg : (plane == 1) ? Alg
                             : (plane == 2) ? Bhg : Blg;
            int rb = (plane < 2) ? bm : bn;
            uint32_t d = st + (uint32_t)(plane * PLANE_B) + (uint32_t)((row * GS + c8) * 2);
            CP16(d, gp + (size_t)(rb + row) * 768 + k0 + c8);
        }
        CP_COMMIT();
    };

    issue(0);
    for (int kc = 0; kc < NCH2; kc++) {
        if (kc + 1 < NCH2) { issue(kc + 1); CP_WAIT1(); }
        else               { CP_WAIT0(); }
        __syncthreads();

        const uint32_t st = sb + (uint32_t)((kc & 1) * STAGE_B);
        const uint32_t pAh = st, pAl = st + PLANE_B, pBh = st + 2*PLANE_B, pBl = st + 3*PLANE_B;
#pragma unroll
        for (int ks = 0; ks < 2; ks++) {
            const int kh = ks * 16;
            uint32_t af[4][4], bfr[4][2], bl2[4][2];
#pragma unroll
            for (int mf = 0; mf < 4; mf++) {
                uint32_t ad = pAh + (uint32_t)(((wm*64 + mf*16 + a_row) * GS + kh + a_cb) * 2);
                ldsm_x4(af[mf][0], af[mf][1], af[mf][2], af[mf][3], ad);
            }
#pragma unroll
            for (int nf = 0; nf < 4; nf++) {
                uint32_t bd = pBh + (uint32_t)(((wn*32 + nf*8 + b_row) * GS + kh + b_cb) * 2);
                asm volatile("ldmatrix.sync.aligned.m8n8.x2.shared.b16 {%0,%1}, [%2];"
                             : "=r"(bfr[nf][0]), "=r"(bfr[nf][1]) : "r"(bd));
            }
#pragma unroll
            for (int mf = 0; mf < 4; mf++)
#pragma unroll
                for (int nf = 0; nf < 4; nf++)
                    mma_bf16(acc[mf][nf], af[mf], bfr[nf]);
#pragma unroll
            for (int nf = 0; nf < 4; nf++) {
                uint32_t bd = pBl + (uint32_t)(((wn*32 + nf*8 + b_row) * GS + kh + b_cb) * 2);
                asm volatile("ldmatrix.sync.aligned.m8n8.x2.shared.b16 {%0,%1}, [%2];"
                             : "=r"(bl2[nf][0]), "=r"(bl2[nf][1]) : "r"(bd));
            }
#pragma unroll
            for (int mf = 0; mf < 4; mf++)
#pragma unroll
                for (int nf = 0; nf < 4; nf++)
                    mma_bf16(acc[mf][nf], af[mf], bl2[nf]);
#pragma unroll
            for (int mf = 0; mf < 4; mf++) {
                uint32_t ad = pAl + (uint32_t)(((wm*64 + mf*16 + a_row) * GS + kh + a_cb) * 2);
                ldsm_x4(af[mf][0], af[mf][1], af[mf][2], af[mf][3], ad);
            }
#pragma unroll
            for (int mf = 0; mf < 4; mf++)
#pragma unroll
                for (int nf = 0; nf < 4; nf++)
                    mma_bf16(acc[mf][nf], af[mf], bfr[nf]);
        }
        __syncthreads();
    }

    const int gr = lane >> 2;
    const int gc = (lane & 3) << 1;
#pragma unroll
    for (int mf = 0; mf < 4; mf++) {
#pragma unroll
        for (int nf = 0; nf < 4; nf++) {
            int n0 = bn + wn*32 + nf*8 + gc;
#pragma unroll
            for (int half = 0; half < 2; half++) {
                int m = bm + wm*64 + mf*16 + gr + half*8;
                float v0 = acc[mf][nf][half*2 + 0];
                float v1 = acc[mf][nf][half*2 + 1];
                if (MODE == 1) {
                    float2 o = make_float2(v0 + bias0[n0], v1 + bias0[n0+1]);
                    *(float2*)(Cout + (size_t)m * 768 + n0) = o;
                } else {
                    int which = n0 / 768;
                    int nn = n0 % 768;
                    int h = nn >> 6, d0 = nn & 63;
                    int b = m >> 10, tok = m & 1023;
                    if (which == 0) {
                        v0 = (v0 + bias0[nn])   * QK_SCALE;
                        v1 = (v1 + bias0[nn+1]) * QK_SCALE;
                    } else if (which == 2) {
                        v0 += bias1[nn];
                        v1 += bias1[nn+1];
                    }
                    uint32_t hp, lp;
                    split2(v0, v1, hp, lp);
                    size_t off = ((size_t)((b*NH + h)*SEQ + tok)) * HD + d0;
                    bf16* ph = (which == 0) ? g_qh : ((which == 1) ? g_kh : g_vh);
                    bf16* pl = (which == 0) ? g_ql : ((which == 1) ? g_kl : g_vl);
                    *(uint32_t*)(ph + off) = hp;
                    *(uint32_t*)(pl + off) = lp;
                }
            }
        }
    }
}

/* ======================================================================
   flash attention, 128-thread CTA (4 warps x 16 q-rows = 64 q-rows),
   cp.async double-buffered K/V tiles, Q overlaid on buffer 0.
   Tile planes: 64 rows x 64 halves = 8 uint4-slots/row x 64 = 512 slots.
   ====================================================================== */
#define FS     72                  /* halves per row */
#define FPLANE_B (64*FS*2)         /* 9216 B */
#define FSTAGE_B (4*FPLANE_B)      /* 36864 B */
#define FLASH_SMEM (2*FSTAGE_B)    /* 73728 B */

__global__ void __launch_bounds__(128) flash_mma()
{
    extern __shared__ __align__(16) bf16 fsm[];
    const uint32_t sb = smem_to_u32(fsm);

    const int tid = threadIdx.x;
    const int lane = tid & 31;
    const int wid = tid >> 5;               /* 0..3 */
    const int bh = blockIdx.y;
    const int qt = blockIdx.x;              /* 0..15, 64-row q tile */
    const int b = bh / NH, h = bh % NH;

    const size_t qbase = ((size_t)bh*SEQ + qt*64) * HD;
    const size_t kvbase = (size_t)bh*SEQ*HD;

    /* ---- stage Q (2 planes, 512 slots each; 8 slots/row) ---- */
#pragma unroll
    for (int u = 0; u < 8; u++) {
        int idx = tid + u * 128;             /* 1024 uint4 slots */
        int plane = idx >> 9;
        int rem = idx & 511;
        int row = rem >> 3;                  /* 0..63 */
        int c8 = (rem & 7) << 3;             /* 0..56 */
        const bf16* src = plane ? g_ql : g_qh;
        *(uint4*)(fsm + plane*(64*FS) + row*FS + c8) =
            *(const uint4*)(src + qbase + (size_t)row*64 + c8);
    }
    __syncthreads();

    uint32_t qh[4][4], ql[4][4];
    {
        int row = wid*16 + (lane & 15);
        int cb = (lane >> 4) << 3;
#pragma unroll
        for (int ks = 0; ks < 4; ks++) {
            uint32_t off = (uint32_t)((row*FS + ks*16 + cb) * 2);
            ldsm_x4(qh[ks][0], qh[ks][1], qh[ks][2], qh[ks][3], sb + off);
            ldsm_x4(ql[ks][0], ql[ks][1], ql[ks][2], ql[ks][3],
                    sb + (uint32_t)FPLANE_B + off);
        }
    }
    __syncthreads();                         /* Q smem dead; KV may overwrite */

    /* cp.async one KV tile (16 per thread; 512 slots/plane, 8 slots/row) */
    auto issue_kv = [&](int j) {
        const uint32_t st = sb + (uint32_t)((j & 1) * FSTAGE_B);
#pragma unroll
        for (int u = 0; u < 16; u++) {
            int idx = tid + u * 128;         /* 2048 slots */
            int plane = idx >> 9;            /* 0..3: kh,kl,vh,vl */
            int rem = idx & 511;
            int row = rem >> 3;              /* 0..63 */
            int c8 = (rem & 7) << 3;         /* 0..56 */
            const bf16* gp = (plane == 0) ? g_kh : (plane == 1) ? g_kl
                             : (plane == 2) ? g_vh : g_vl;
            uint32_t d = st + (uint32_t)(plane * FPLANE_B) + (uint32_t)((row*FS + c8) * 2);
            CP16(d, gp + kvbase + (size_t)(j*64 + row)*64 + c8);
        }
        CP_COMMIT();
    };

    float o[8][4];
#pragma unroll
    for (int i = 0; i < 8; i++)
#pragma unroll
        for (int t = 0; t < 4; t++) o[i][t] = 0.f;
    float m0 = -1e30f, m1 = -1e30f, l0 = 0.f, l1 = 0.f;

    const int gr = lane >> 2;
    const int gc = (lane & 3) << 1;
    const int frow = lane & 15;
    const int fcb = (lane >> 4) << 3;

    issue_kv(0);
    for (int kt = 0; kt < SEQ/64; kt++) {
        /* prefetch mask for THIS tile into regs (consumed after S MMAs) */
        float2 mk[8];
#pragma unroll
        for (int nf = 0; nf < 8; nf++)
            mk[nf] = *(const float2*)(g_maskf + b*SEQ + kt*64 + nf*8 + gc);

        if (kt + 1 < SEQ/64) { issue_kv(kt + 1); CP_WAIT1(); }
        else                 { CP_WAIT0(); }
        __syncthreads();

        const uint32_t st = sb + (uint32_t)((kt & 1) * FSTAGE_B);
        const uint32_t pKh = st, pKl = st + FPLANE_B;
        const uint32_t pVh = st + 2*FPLANE_B, pVl = st + 3*FPLANE_B;

        /* ---- S = (Qh+Ql)(Kh+Kl)^T, 3 passes ---- */
        float s4[8][4];
#pragma unroll
        for (int i = 0; i < 8; i++)
#pragma unroll
            for (int t = 0; t < 4; t++) s4[i][t] = 0.f;

#pragma unroll
        for (int ks = 0; ks < 4; ks++) {
#pragma unroll
            for (int np = 0; np < 4; np++) {
                uint32_t off = (uint32_t)(((np*16 + frow)*FS + ks*16 + fcb) * 2);
                uint32_t r0, r1, r2, r3, kb0[2], kb1[2];
                ldsm_x4(r0, r1, r2, r3, pKh + off);
                kb0[0] = r0; kb0[1] = r2; kb1[0] = r1; kb1[1] = r3;
                mma_bf16(s4[2*np],   qh[ks], kb0);
                mma_bf16(s4[2*np+1], qh[ks], kb1);
                mma_bf16(s4[2*np],   ql[ks], kb0);
                mma_bf16(s4[2*np+1], ql[ks], kb1);
                ldsm_x4(r0, r1, r2, r3, pKl + off);
                kb0[0] = r0; kb0[1] = r2; kb1[0] = r1; kb1[1] = r3;
                mma_bf16(s4[2*np],   qh[ks], kb0);
                mma_bf16(s4[2*np+1], qh[ks], kb1);
            }
        }

        /* ---- mask + online softmax ---- */
        float tm0 = -1e30f, tm1 = -1e30f;
#pragma unroll
        for (int nf = 0; nf < 8; nf++) {
            s4[nf][0] += mk[nf].x; s4[nf][1] += mk[nf].y;
            s4[nf][2] += mk[nf].x; s4[nf][3] += mk[nf].y;
            tm0 = fmaxf(tm0, fmaxf(s4[nf][0], s4[nf][1]));
            tm1 = fmaxf(tm1, fmaxf(s4[nf][2], s4[nf][3]));
        }
        tm0 = fmaxf(tm0, __shfl_xor_sync(0xffffffffu, tm0, 1));
        tm0 = fmaxf(tm0, __shfl_xor_sync(0xffffffffu, tm0, 2));
        tm1 = fmaxf(tm1, __shfl_xor_sync(0xffffffffu, tm1, 1));
        tm1 = fmaxf(tm1, __shfl_xor_sync(0xffffffffu, tm1, 2));
        float mn0 = fmaxf(m0, tm0), mn1 = fmaxf(m1, tm1);
        float al0 = __expf(m0 - mn0), al1 = __expf(m1 - mn1);
        m0 = mn0; m1 = mn1;
        float ls0 = 0.f, ls1 = 0.f;
#pragma unroll
        for (int nf = 0; nf < 8; nf++) {
            s4[nf][0] = __expf(s4[nf][0] - mn0);
            s4[nf][1] = __expf(s4[nf][1] - mn0);
            s4[nf][2] = __expf(s4[nf][2] - mn1);
            s4[nf][3] = __expf(s4[nf][3] - mn1);
            ls0 += s4[nf][0] + s4[nf][1];
            ls1 += s4[nf][2] + s4[nf][3];
        }
        ls0 += __shfl_xor_sync(0xffffffffu, ls0, 1);
        ls0 += __shfl_xor_sync(0xffffffffu, ls0, 2);
        ls1 += __shfl_xor_sync(0xffffffffu, ls1, 1);
        ls1 += __shfl_xor_sync(0xffffffffu, ls1, 2);
        l0 = l0 * al0 + ls0;
        l1 = l1 * al1 + ls1;
#pragma unroll
        for (int nf = 0; nf < 8; nf++) {
            o[nf][0] *= al0; o[nf][1] *= al0;
            o[nf][2] *= al1; o[nf][3] *= al1;
        }

        /* ---- O += (Ph+Pl)(Vh+Vl), 3 passes; P packed from registers ---- */
#pragma unroll
        for (int ksv = 0; ksv < 4; ksv++) {
            uint32_t ph[4], pl[4];
            split2(s4[2*ksv][0],   s4[2*ksv][1],   ph[0], pl[0]);
            split2(s4[2*ksv][2],   s4[2*ksv][3],   ph[1], pl[1]);
            split2(s4[2*ksv+1][0], s4[2*ksv+1][1], ph[2], pl[2]);
            split2(s4[2*ksv+1][2], s4[2*ksv+1][3], ph[3], pl[3]);
#pragma unroll
            for (int np = 0; np < 4; np++) {
                uint32_t off = (uint32_t)(((ksv*16 + frow)*FS + np*16 + fcb) * 2);
                uint32_t r0, r1, r2, r3, vh0[2], vh1[2], vl0[2], vl1[2];
                ldsm_x4_t(r0, r1, r2, r3, pVh + off);
                vh0[0] = r0; vh0[1] = r1; vh1[0] = r2; vh1[1] = r3;
                ldsm_x4_t(r0, r1, r2, r3, pVl + off);
                vl0[0] = r0; vl0[1] = r1; vl1[0] = r2; vl1[1] = r3;
                mma_bf16(o[2*np],   ph, vh0);
                mma_bf16(o[2*np+1], ph, vh1);
                mma_bf16(o[2*np],   ph, vl0);
                mma_bf16(o[2*np+1], ph, vl1);
                mma_bf16(o[2*np],   pl, vh0);
                mma_bf16(o[2*np+1], pl, vh1);
            }
        }
        __syncthreads();
    }

    /* ---- finalize ---- */
    float inv0 = 1.f / l0, inv1 = 1.f / l1;
    int tok0 = qt*64 + wid*16 + gr;
    size_t r0g = ((size_t)(b*SEQ + tok0)) * DIMC + h*HD;
    size_t r1g = r0g + 8*DIMC;
#pragma unroll
    for (int nf = 0; nf < 8; nf++) {
        int d = nf*8 + gc;
        uint32_t hp, lp;
        split2(o[nf][0]*inv0, o[nf][1]*inv0, hp, lp);
        *(uint32_t*)(g_aoh + r0g + d) = hp;
        *(uint32_t*)(g_aol + r0g + d) = lp;
        split2(o[nf][2]*inv1, o[nf][3]*inv1, hp, lp);
        *(uint32_t*)(g_aoh + r1g + d) = hp;
        *(uint32_t*)(g_aol + r1g + d) = lp;
    }
}

/* ---------------- launcher ---------------- */
extern "C" void kernel_launch(void* const* d_in, const int* in_sizes, int n_in,
                              void* d_out, int out_size)
{
    const float* x           = (const float*)d_in[0];
    const unsigned char* msk = (const unsigned char*)d_in[1];
    const float* qkv_w       = (const float*)d_in[2];
    const float* q_bias      = (const float*)d_in[3];
    const float* v_bias      = (const float*)d_in[4];
    const float* proj_w      = (const float*)d_in[5];
    const float* proj_b      = (const float*)d_in[6];
    float* out               = (float*)d_out;

    (void)in_sizes; (void)n_in; (void)out_size;

    cudaFuncSetAttribute(gemm_mma<0>, cudaFuncAttributeMaxDynamicSharedMemorySize, GEMM_SMEM);
    cudaFuncSetAttribute(gemm_mma<1>, cudaFuncAttributeMaxDynamicSharedMemorySize, GEMM_SMEM);
    cudaFuncSetAttribute(flash_mma, cudaFuncAttributeMaxDynamicSharedMemorySize, FLASH_SMEM);

    detect_mask_kernel<<<1, 256>>>(msk);
    maskf_kernel<<<(BATCH*SEQ + 255)/256, 256>>>(msk);

    bf16 *xh, *xl, *wqh, *wql, *wph, *wpl;
    cudaGetSymbolAddress((void**)&xh,  g_xh);  cudaGetSymbolAddress((void**)&xl,  g_xl);
    cudaGetSymbolAddress((void**)&wqh, g_wqh); cudaGetSymbolAddress((void**)&wql, g_wql);
    cudaGetSymbolAddress((void**)&wph, g_wph); cudaGetSymbolAddress((void**)&wpl, g_wpl);

    split_kernel<<<1024, 256>>>(x,      xh,  xl,  M_TOT*DIMC/4);
    split_kernel<<<1024, 256>>>(qkv_w,  wqh, wql, 3*DIMC*DIMC/4);
    split_kernel<<<512,  256>>>(proj_w, wph, wpl, DIMC*DIMC/4);

    gemm_mma<0><<<dim3(2304/128, M_TOT/128), 256, GEMM_SMEM>>>(
        xh, xl, wqh, wql, q_bias, v_bias, nullptr);

    flash_mma<<<dim3(SEQ/64, BH), 128, FLASH_SMEM>>>();

    bf16 *aoh, *aol;
    cudaGetSymbolAddress((void**)&aoh, g_aoh); cudaGetSymbolAddress((void**)&aol, g_aol);
    gemm_mma<1><<<dim3(768/128, M_TOT/128), 256, GEMM_SMEM>>>(
        aoh, aol, wph, wpl, proj_b, nullptr, out);
}

// round 12
// speedup vs baseline: 2.7936x; 1.0372x over previous
#include <cuda_runtime.h>
#include <cuda_bf16.h>
#include <math.h>
#include <cstdint>

#define BATCH 8
#define SEQ   1024
#define DIMC  768
#define NH    12
#define HD    64
#define M_TOT (BATCH*SEQ)     /* 8192 */
#define QK_SCALE 0.125f
#define BH    (BATCH*NH)      /* 96 */

typedef __nv_bfloat16 bf16;

/* ---------------- scratch (no cudaMalloc allowed) ---------------- */
__device__ bf16 g_xh[M_TOT*DIMC],  g_xl[M_TOT*DIMC];
__device__ bf16 g_wqh[3*DIMC*DIMC], g_wql[3*DIMC*DIMC];
__device__ bf16 g_wph[DIMC*DIMC],  g_wpl[DIMC*DIMC];
__device__ bf16 g_qh[BH*SEQ*HD], g_ql[BH*SEQ*HD];
__device__ bf16 g_kh[BH*SEQ*HD], g_kl[BH*SEQ*HD];
__device__ bf16 g_vh[BH*SEQ*HD], g_vl[BH*SEQ*HD];
__device__ bf16 g_aoh[M_TOT*DIMC], g_aol[M_TOT*DIMC];
__device__ float g_maskf[BATCH*SEQ];

__device__ __forceinline__ uint32_t smem_to_u32(const void* p) {
    uint32_t a;
    asm("{ .reg .u64 t; cvta.to.shared.u64 t, %1; cvt.u32.u64 %0, t; }" : "=r"(a) : "l"(p));
    return a;
}

/* ---------------- baseline-PTX tensor / async ops ---------------- */
__device__ __forceinline__ void ldsm_x4(uint32_t& a0, uint32_t& a1, uint32_t& a2,
                                        uint32_t& a3, uint32_t addr) {
    asm volatile("ldmatrix.sync.aligned.m8n8.x4.shared.b16 {%0,%1,%2,%3}, [%4];"
                 : "=r"(a0), "=r"(a1), "=r"(a2), "=r"(a3) : "r"(addr));
}
__device__ __forceinline__ void ldsm_x4_t(uint32_t& a0, uint32_t& a1, uint32_t& a2,
                                          uint32_t& a3, uint32_t addr) {
    asm volatile("ldmatrix.sync.aligned.m8n8.x4.trans.shared.b16 {%0,%1,%2,%3}, [%4];"
                 : "=r"(a0), "=r"(a1), "=r"(a2), "=r"(a3) : "r"(addr));
}
__device__ __forceinline__ void mma_bf16(float (&c)[4], const uint32_t (&a)[4],
                                         const uint32_t (&b)[2]) {
    asm volatile("mma.sync.aligned.m16n8k16.row.col.f32.bf16.bf16.f32 "
                 "{%0,%1,%2,%3}, {%4,%5,%6,%7}, {%8,%9}, {%0,%1,%2,%3};"
                 : "+f"(c[0]), "+f"(c[1]), "+f"(c[2]), "+f"(c[3])
                 : "r"(a[0]), "r"(a[1]), "r"(a[2]), "r"(a[3]), "r"(b[0]), "r"(b[1]));
}
#define CP16(dst, src) \
    asm volatile("cp.async.cg.shared.global [%0], [%1], 16;" :: "r"(dst), "l"(src))
#define CP_COMMIT() asm volatile("cp.async.commit_group;" ::: "memory")
#define CP_WAIT1()  asm volatile("cp.async.wait_group 1;" ::: "memory")
#define CP_WAIT0()  asm volatile("cp.async.wait_group 0;" ::: "memory")

__device__ __forceinline__ void split2(float a, float b, uint32_t& hi, uint32_t& lo) {
    bf16 ha = __float2bfloat16(a), hb = __float2bfloat16(b);
    bf16 la = __float2bfloat16(a - __bfloat162float(ha));
    bf16 lb = __float2bfloat16(b - __bfloat162float(hb));
    hi = ((uint32_t)__bfloat16_as_ushort(hb) << 16) | __bfloat16_as_ushort(ha);
    lo = ((uint32_t)__bfloat16_as_ushort(lb) << 16) | __bfloat16_as_ushort(la);
}

/* ---------------- preprocessing: one fused split + one mask kernel -------- */
#define SN0 (M_TOT*DIMC/4)
#define SN1 (3*DIMC*DIMC/4)
#define SN2 (DIMC*DIMC/4)

__global__ void split_all_kernel(const float* __restrict__ x,
                                 const float* __restrict__ wq,
                                 const float* __restrict__ wp) {
    int i = blockIdx.x * blockDim.x + threadIdx.x;
    int stride = gridDim.x * blockDim.x;
    const int total = SN0 + SN1 + SN2;
    for (; i < total; i += stride) {
        const float* s; bf16 *hp, *lp; int j = i;
        if (j < SN0)            { s = x;  hp = g_xh;  lp = g_xl; }
        else if (j < SN0 + SN1) { j -= SN0; s = wq; hp = g_wqh; lp = g_wql; }
        else                    { j -= SN0 + SN1; s = wp; hp = g_wph; lp = g_wpl; }
        float4 v = ((const float4*)s)[j];
        uint32_t h0, l0, h1, l1;
        split2(v.x, v.y, h0, l0);
        split2(v.z, v.w, h1, l1);
        ((uint2*)hp)[j] = make_uint2(h0, h1);
        ((uint2*)lp)[j] = make_uint2(l0, l1);
    }
}

/* single block: sniff mask dtype (bool vs int32 serialization), write floats */
__global__ void mask_prep_kernel(const unsigned char* __restrict__ m) {
    __shared__ int any;
    if (threadIdx.x == 0) any = 0;
    __syncthreads();
    int loc = 0;
    for (int i = threadIdx.x; i < BATCH*SEQ; i += blockDim.x)
        if ((i & 3) && m[i]) loc = 1;
    if (loc) any = 1;
    __syncthreads();
    const bool mbyte = (any != 0);
    const int* mi = (const int*)m;
    for (int i = threadIdx.x; i < BATCH*SEQ; i += blockDim.x) {
        bool msk = mbyte ? (m[i] != 0) : (mi[i] != 0);
        g_maskf[i] = msk ? -1e30f : 0.f;
    }
}

/* ======================================================================
   cp.async double-buffered warp-MMA split-bf16 NT GEMM (unchanged R10).
   CTA 128x128, 8 warps (2x4), warp 64x32. KC=32, 2 stages. 2 CTAs/SM.
   ====================================================================== */
#define KC2    32
#define NCH2   (768/KC2)          /* 24 */
#define GS     40                 /* halves per row (80 B, ldmatrix-safe) */
#define PLANE_B (128*GS*2)        /* 10240 B */
#define STAGE_B (4*PLANE_B)       /* 40960 B */
#define GEMM_SMEM (2*STAGE_B)     /* 81920 B */

template<int MODE>
__global__ void __launch_bounds__(256, 2) gemm_mma(
    const bf16* __restrict__ Ahg, const bf16* __restrict__ Alg,
    const bf16* __restrict__ Bhg, const bf16* __restrict__ Blg,
    const float* __restrict__ bias0, const float* __restrict__ bias1,
    float* __restrict__ Cout)
{
    extern __shared__ __align__(16) bf16 smb[];
    const uint32_t sb = smem_to_u32(smb);

    const int tid = threadIdx.x;
    const int lane = tid & 31;
    const int wid = tid >> 5;
    const int wm = wid >> 2, wn = wid & 3;
    const int bm = blockIdx.y * 128, bn = blockIdx.x * 128;

    const int a_row = lane & 15, a_cb = (lane >> 4) << 3;
    const int l2 = lane & 15;
    const int b_row = l2 & 7,  b_cb = ((l2 >> 3) & 1) << 3;

    float acc[4][4][4];
#pragma unroll
    for (int i = 0; i < 4; i++)
#pragma unroll
        for (int j = 0; j < 4; j++)
#pragma unroll
            for (int t = 0; t < 4; t++) acc[i][j][t] = 0.f;

    auto issue = [&](int kc) {
        const int k0 = kc * KC2;
        const uint32_t st = sb + (uint32_t)((kc & 1) * STAGE_B);
#pragma unroll
        for (int u = 0; u < 8; u++) {
            int idx = tid + u * 256;
            int plane = idx >> 9;
            int rem = idx & 511;
            int row = rem >> 2;
            int c8 = (rem & 3) << 3;
            const bf16* gp = (plane == 0) ? Ahg : (plane == 1) ? Alg
                             : (plane == 2) ? Bhg : Blg;
            int rb = (plane < 2) ? bm : bn;
            uint32_t d = st + (uint32_t)(plane * PLANE_B) + (uint32_t)((row * GS + c8) * 2);
            CP16(d, gp + (size_t)(rb + row) * 768 + k0 + c8);
        }
        CP_COMMIT();
    };

    issue(0);
    for (int kc = 0; kc < NCH2; kc++) {
        if (kc + 1 < NCH2) { issue(kc + 1); CP_WAIT1(); }
        else               { CP_WAIT0(); }
        __syncthreads();

        const uint32_t st = sb + (uint32_t)((kc & 1) * STAGE_B);
        const uint32_t pAh = st, pAl = st + PLANE_B, pBh = st + 2*PLANE_B, pBl = st + 3*PLANE_B;
#pragma unroll
        for (int ks = 0; ks < 2; ks++) {
            const int kh = ks * 16;
            uint32_t af[4][4], bfr[4][2], bl2[4][2];
#pragma unroll
            for (int mf = 0; mf < 4; mf++) {
                uint32_t ad = pAh + (uint32_t)(((wm*64 + mf*16 + a_row) * GS + kh + a_cb) * 2);
                ldsm_x4(af[mf][0], af[mf][1], af[mf][2], af[mf][3], ad);
            }
#pragma unroll
            for (int nf = 0; nf < 4; nf++) {
                uint32_t bd = pBh + (uint32_t)(((wn*32 + nf*8 + b_row) * GS + kh + b_cb) * 2);
                asm volatile("ldmatrix.sync.aligned.m8n8.x2.shared.b16 {%0,%1}, [%2];"
                             : "=r"(bfr[nf][0]), "=r"(bfr[nf][1]) : "r"(bd));
            }
#pragma unroll
            for (int mf = 0; mf < 4; mf++)
#pragma unroll
                for (int nf = 0; nf < 4; nf++)
                    mma_bf16(acc[mf][nf], af[mf], bfr[nf]);
#pragma unroll
            for (int nf = 0; nf < 4; nf++) {
                uint32_t bd = pBl + (uint32_t)(((wn*32 + nf*8 + b_row) * GS + kh + b_cb) * 2);
                asm volatile("ldmatrix.sync.aligned.m8n8.x2.shared.b16 {%0,%1}, [%2];"
                             : "=r"(bl2[nf][0]), "=r"(bl2[nf][1]) : "r"(bd));
            }
#pragma unroll
            for (int mf = 0; mf < 4; mf++)
#pragma unroll
                for (int nf = 0; nf < 4; nf++)
                    mma_bf16(acc[mf][nf], af[mf], bl2[nf]);
#pragma unroll
            for (int mf = 0; mf < 4; mf++) {
                uint32_t ad = pAl + (uint32_t)(((wm*64 + mf*16 + a_row) * GS + kh + a_cb) * 2);
                ldsm_x4(af[mf][0], af[mf][1], af[mf][2], af[mf][3], ad);
            }
#pragma unroll
            for (int mf = 0; mf < 4; mf++)
#pragma unroll
                for (int nf = 0; nf < 4; nf++)
                    mma_bf16(acc[mf][nf], af[mf], bfr[nf]);
        }
        __syncthreads();
    }

    const int gr = lane >> 2;
    const int gc = (lane & 3) << 1;
#pragma unroll
    for (int mf = 0; mf < 4; mf++) {
#pragma unroll
        for (int nf = 0; nf < 4; nf++) {
            int n0 = bn + wn*32 + nf*8 + gc;
#pragma unroll
            for (int half = 0; half < 2; half++) {
                int m = bm + wm*64 + mf*16 + gr + half*8;
                float v0 = acc[mf][nf][half*2 + 0];
                float v1 = acc[mf][nf][half*2 + 1];
                if (MODE == 1) {
                    float2 o = make_float2(v0 + bias0[n0], v1 + bias0[n0+1]);
                    *(float2*)(Cout + (size_t)m * 768 + n0) = o;
                } else {
                    int which = n0 / 768;
                    int nn = n0 % 768;
                    int h = nn >> 6, d0 = nn & 63;
                    int b = m >> 10, tok = m & 1023;
                    if (which == 0) {
                        v0 = (v0 + bias0[nn])   * QK_SCALE;
                        v1 = (v1 + bias0[nn+1]) * QK_SCALE;
                    } else if (which == 2) {
                        v0 += bias1[nn];
                        v1 += bias1[nn+1];
                    }
                    uint32_t hp, lp;
                    split2(v0, v1, hp, lp);
                    size_t off = ((size_t)((b*NH + h)*SEQ + tok)) * HD + d0;
                    bf16* ph = (which == 0) ? g_qh : ((which == 1) ? g_kh : g_vh);
                    bf16* pl = (which == 0) ? g_ql : ((which == 1) ? g_kl : g_vl);
                    *(uint32_t*)(ph + off) = hp;
                    *(uint32_t*)(pl + off) = lp;
                }
            }
        }
    }
}

/* ======================================================================
   flash attention, 128-thread CTA (4 warps x 16 q-rows),
   cp.async double-buffered K/V tiles, WIDE-ILP MMA ordering:
   all 8 B-fragments staged per pass so accumulator chains are distance-8.
   ====================================================================== */
#define FS     72                  /* halves per row */
#define FPLANE_B (64*FS*2)         /* 9216 B */
#define FSTAGE_B (4*FPLANE_B)      /* 36864 B */
#define FLASH_SMEM (2*FSTAGE_B)    /* 73728 B */

__global__ void __launch_bounds__(128, 3) flash_mma()
{
    extern __shared__ __align__(16) bf16 fsm[];
    const uint32_t sb = smem_to_u32(fsm);

    const int tid = threadIdx.x;
    const int lane = tid & 31;
    const int wid = tid >> 5;               /* 0..3 */
    const int bh = blockIdx.y;
    const int qt = blockIdx.x;              /* 0..15, 64-row q tile */
    const int b = bh / NH, h = bh % NH;

    const size_t qbase = ((size_t)bh*SEQ + qt*64) * HD;
    const size_t kvbase = (size_t)bh*SEQ*HD;

    /* ---- stage Q (2 planes; 8 uint4-slots/row) ---- */
#pragma unroll
    for (int u = 0; u < 8; u++) {
        int idx = tid + u * 128;
        int plane = idx >> 9;
        int rem = idx & 511;
        int row = rem >> 3;
        int c8 = (rem & 7) << 3;
        const bf16* src = plane ? g_ql : g_qh;
        *(uint4*)(fsm + plane*(64*FS) + row*FS + c8) =
            *(const uint4*)(src + qbase + (size_t)row*64 + c8);
    }
    __syncthreads();

    uint32_t qh[4][4], ql[4][4];
    {
        int row = wid*16 + (lane & 15);
        int cb = (lane >> 4) << 3;
#pragma unroll
        for (int ks = 0; ks < 4; ks++) {
            uint32_t off = (uint32_t)((row*FS + ks*16 + cb) * 2);
            ldsm_x4(qh[ks][0], qh[ks][1], qh[ks][2], qh[ks][3], sb + off);
            ldsm_x4(ql[ks][0], ql[ks][1], ql[ks][2], ql[ks][3],
                    sb + (uint32_t)FPLANE_B + off);
        }
    }
    __syncthreads();                         /* Q smem dead; KV may overwrite */

    auto issue_kv = [&](int j) {
        const uint32_t st = sb + (uint32_t)((j & 1) * FSTAGE_B);
#pragma unroll
        for (int u = 0; u < 16; u++) {
            int idx = tid + u * 128;
            int plane = idx >> 9;            /* 0..3: kh,kl,vh,vl */
            int rem = idx & 511;
            int row = rem >> 3;
            int c8 = (rem & 7) << 3;
            const bf16* gp = (plane == 0) ? g_kh : (plane == 1) ? g_kl
                             : (plane == 2) ? g_vh : g_vl;
            uint32_t d = st + (uint32_t)(plane * FPLANE_B) + (uint32_t)((row*FS + c8) * 2);
            CP16(d, gp + kvbase + (size_t)(j*64 + row)*64 + c8);
        }
        CP_COMMIT();
    };

    float o[8][4];
#pragma unroll
    for (int i = 0; i < 8; i++)
#pragma unroll
        for (int t = 0; t < 4; t++) o[i][t] = 0.f;
    float m0 = -1e30f, m1 = -1e30f, l0 = 0.f, l1 = 0.f;

    const int gr = lane >> 2;
    const int gc = (lane & 3) << 1;
    const int frow = lane & 15;
    const int fcb = (lane >> 4) << 3;

    issue_kv(0);
    for (int kt = 0; kt < SEQ/64; kt++) {
        float2 mk[8];
#pragma unroll
        for (int nf = 0; nf < 8; nf++)
            mk[nf] = *(const float2*)(g_maskf + b*SEQ + kt*64 + nf*8 + gc);

        if (kt + 1 < SEQ/64) { issue_kv(kt + 1); CP_WAIT1(); }
        else                 { CP_WAIT0(); }
        __syncthreads();

        const uint32_t st = sb + (uint32_t)((kt & 1) * FSTAGE_B);
        const uint32_t pKh = st, pKl = st + FPLANE_B;
        const uint32_t pVh = st + 2*FPLANE_B, pVl = st + 3*FPLANE_B;

        /* ---- S = (Qh+Ql)(Kh+Kl)^T, 3 wide passes per ks ---- */
        float s4[8][4];
#pragma unroll
        for (int i = 0; i < 8; i++)
#pragma unroll
            for (int t = 0; t < 4; t++) s4[i][t] = 0.f;

#pragma unroll
        for (int ks = 0; ks < 4; ks++) {
            uint32_t kbh[8][2], kbl[8][2];
#pragma unroll
            for (int np = 0; np < 4; np++) {
                uint32_t off = (uint32_t)(((np*16 + frow)*FS + ks*16 + fcb) * 2);
                uint32_t r0, r1, r2, r3;
                ldsm_x4(r0, r1, r2, r3, pKh + off);
                kbh[2*np][0] = r0; kbh[2*np][1] = r2;
                kbh[2*np+1][0] = r1; kbh[2*np+1][1] = r3;
                ldsm_x4(r0, r1, r2, r3, pKl + off);
                kbl[2*np][0] = r0; kbl[2*np][1] = r2;
                kbl[2*np+1][0] = r1; kbl[2*np+1][1] = r3;
            }
#pragma unroll
            for (int nf = 0; nf < 8; nf++) mma_bf16(s4[nf], qh[ks], kbh[nf]);
#pragma unroll
            for (int nf = 0; nf < 8; nf++) mma_bf16(s4[nf], ql[ks], kbh[nf]);
#pragma unroll
            for (int nf = 0; nf < 8; nf++) mma_bf16(s4[nf], qh[ks], kbl[nf]);
        }

        /* ---- mask + online softmax ---- */
        float tm0 = -1e30f, tm1 = -1e30f;
#pragma unroll
        for (int nf = 0; nf < 8; nf++) {
            s4[nf][0] += mk[nf].x; s4[nf][1] += mk[nf].y;
            s4[nf][2] += mk[nf].x; s4[nf][3] += mk[nf].y;
            tm0 = fmaxf(tm0, fmaxf(s4[nf][0], s4[nf][1]));
            tm1 = fmaxf(tm1, fmaxf(s4[nf][2], s4[nf][3]));
        }
        tm0 = fmaxf(tm0, __shfl_xor_sync(0xffffffffu, tm0, 1));
        tm0 = fmaxf(tm0, __shfl_xor_sync(0xffffffffu, tm0, 2));
        tm1 = fmaxf(tm1, __shfl_xor_sync(0xffffffffu, tm1, 1));
        tm1 = fmaxf(tm1, __shfl_xor_sync(0xffffffffu, tm1, 2));
        float mn0 = fmaxf(m0, tm0), mn1 = fmaxf(m1, tm1);
        float al0 = __expf(m0 - mn0), al1 = __expf(m1 - mn1);
        m0 = mn0; m1 = mn1;
        float ls0 = 0.f, ls1 = 0.f;
#pragma unroll
        for (int nf = 0; nf < 8; nf++) {
            s4[nf][0] = __expf(s4[nf][0] - mn0);
            s4[nf][1] = __expf(s4[nf][1] - mn0);
            s4[nf][2] = __expf(s4[nf][2] - mn1);
            s4[nf][3] = __expf(s4[nf][3] - mn1);
            ls0 += s4[nf][0] + s4[nf][1];
            ls1 += s4[nf][2] + s4[nf][3];
        }
        ls0 += __shfl_xor_sync(0xffffffffu, ls0, 1);
        ls0 += __shfl_xor_sync(0xffffffffu, ls0, 2);
        ls1 += __shfl_xor_sync(0xffffffffu, ls1, 1);
        ls1 += __shfl_xor_sync(0xffffffffu, ls1, 2);
        l0 = l0 * al0 + ls0;
        l1 = l1 * al1 + ls1;
#pragma unroll
        for (int nf = 0; nf < 8; nf++) {
            o[nf][0] *= al0; o[nf][1] *= al0;
            o[nf][2] *= al1; o[nf][3] *= al1;
        }

        /* ---- O += (Ph+Pl)(Vh+Vl), 3 wide passes per ksv ---- */
#pragma unroll
        for (int ksv = 0; ksv < 4; ksv++) {
            uint32_t ph[4], pl[4];
            split2(s4[2*ksv][0],   s4[2*ksv][1],   ph[0], pl[0]);
            split2(s4[2*ksv][2],   s4[2*ksv][3],   ph[1], pl[1]);
            split2(s4[2*ksv+1][0], s4[2*ksv+1][1], ph[2], pl[2]);
            split2(s4[2*ksv+1][2], s4[2*ksv+1][3], ph[3], pl[3]);
            uint32_t vhf[8][2], vlf[8][2];
#pragma unroll
            for (int np = 0; np < 4; np++) {
                uint32_t off = (uint32_t)(((ksv*16 + frow)*FS + np*16 + fcb) * 2);
                uint32_t r0, r1, r2, r3;
                ldsm_x4_t(r0, r1, r2, r3, pVh + off);
                vhf[2*np][0] = r0; vhf[2*np][1] = r1;
                vhf[2*np+1][0] = r2; vhf[2*np+1][1] = r3;
                ldsm_x4_t(r0, r1, r2, r3, pVl + off);
                vlf[2*np][0] = r0; vlf[2*np][1] = r1;
                vlf[2*np+1][0] = r2; vlf[2*np+1][1] = r3;
            }
#pragma unroll
            for (int nf = 0; nf < 8; nf++) mma_bf16(o[nf], ph, vhf[nf]);
#pragma unroll
            for (int nf = 0; nf < 8; nf++) mma_bf16(o[nf], ph, vlf[nf]);
#pragma unroll
            for (int nf = 0; nf < 8; nf++) mma_bf16(o[nf], pl, vhf[nf]);
        }
        __syncthreads();
    }

    /* ---- finalize ---- */
    float inv0 = 1.f / l0, inv1 = 1.f / l1;
    int tok0 = qt*64 + wid*16 + gr;
    size_t r0g = ((size_t)(b*SEQ + tok0)) * DIMC + h*HD;
    size_t r1g = r0g + 8*DIMC;
#pragma unroll
    for (int nf = 0; nf < 8; nf++) {
        int d = nf*8 + gc;
        uint32_t hp, lp;
        split2(o[nf][0]*inv0, o[nf][1]*inv0, hp, lp);
        *(uint32_t*)(g_aoh + r0g + d) = hp;
        *(uint32_t*)(g_aol + r0g + d) = lp;
        split2(o[nf][2]*inv1, o[nf][3]*inv1, hp, lp);
        *(uint32_t*)(g_aoh + r1g + d) = hp;
        *(uint32_t*)(g_aol + r1g + d) = lp;
    }
}

/* ---------------- launcher ---------------- */
extern "C" void kernel_launch(void* const* d_in, const int* in_sizes, int n_in,
                              void* d_out, int out_size)
{
    const float* x           = (const float*)d_in[0];
    const unsigned char* msk = (const unsigned char*)d_in[1];
    const float* qkv_w       = (const float*)d_in[2];
    const float* q_bias      = (const float*)d_in[3];
    const float* v_bias      = (const float*)d_in[4];
    const float* proj_w      = (const float*)d_in[5];
    const float* proj_b      = (const float*)d_in[6];
    float* out               = (float*)d_out;

    (void)in_sizes; (void)n_in; (void)out_size;

    cudaFuncSetAttribute(gemm_mma<0>, cudaFuncAttributeMaxDynamicSharedMemorySize, GEMM_SMEM);
    cudaFuncSetAttribute(gemm_mma<1>, cudaFuncAttributeMaxDynamicSharedMemorySize, GEMM_SMEM);
    cudaFuncSetAttribute(flash_mma, cudaFuncAttributeMaxDynamicSharedMemorySize, FLASH_SMEM);

    mask_prep_kernel<<<1, 1024>>>(msk);
    split_all_kernel<<<2048, 256>>>(x, qkv_w, proj_w);

    bf16 *xh, *xl, *wqh, *wql, *wph, *wpl;
    cudaGetSymbolAddress((void**)&xh,  g_xh);  cudaGetSymbolAddress((void**)&xl,  g_xl);
    cudaGetSymbolAddress((void**)&wqh, g_wqh); cudaGetSymbolAddress((void**)&wql, g_wql);
    cudaGetSymbolAddress((void**)&wph, g_wph); cudaGetSymbolAddress((void**)&wpl, g_wpl);

    gemm_mma<0><<<dim3(2304/128, M_TOT/128), 256, GEMM_SMEM>>>(
        xh, xl, wqh, wql, q_bias, v_bias, nullptr);

    flash_mma<<<dim3(SEQ/64, BH), 128, FLASH_SMEM>>>();

    bf16 *aoh, *aol;
    cudaGetSymbolAddress((void**)&aoh, g_aoh); cudaGetSymbolAddress((void**)&aol, g_aol);
    gemm_mma<1><<<dim3(768/128, M_TOT/128), 256, GEMM_SMEM>>>(
        aoh, aol, wph, wpl, proj_b, nullptr, out);
}

// round 13
// speedup vs baseline: 2.9868x; 1.0691x over previous
#include <cuda_runtime.h>
#include <cuda_bf16.h>
#include <math.h>
#include <cstdint>

#define BATCH 8
#define SEQ   1024
#define DIMC  768
#define NH    12
#define HD    64
#define M_TOT (BATCH*SEQ)     /* 8192 */
#define QK_SCALE 0.125f
#define BH    (BATCH*NH)      /* 96 */

typedef __nv_bfloat16 bf16;

/* ---------------- scratch (no cudaMalloc allowed) ---------------- */
__device__ bf16 g_xh[M_TOT*DIMC],  g_xl[M_TOT*DIMC];
__device__ bf16 g_wqh[3*DIMC*DIMC], g_wql[3*DIMC*DIMC];
__device__ bf16 g_wph[DIMC*DIMC],  g_wpl[DIMC*DIMC];
__device__ bf16 g_qh[BH*SEQ*HD], g_ql[BH*SEQ*HD];
__device__ bf16 g_kh[BH*SEQ*HD], g_kl[BH*SEQ*HD];
__device__ bf16 g_vh[BH*SEQ*HD], g_vl[BH*SEQ*HD];
__device__ bf16 g_aoh[M_TOT*DIMC], g_aol[M_TOT*DIMC];
__device__ int   g_kidx[BATCH*SEQ];     /* compacted key indices per batch */
__device__ float g_cmask[BATCH*SEQ];    /* 0 for valid slot, -1e30 for pad */
__device__ int   g_kcnt[BATCH];

__device__ __forceinline__ uint32_t smem_to_u32(const void* p) {
    uint32_t a;
    asm("{ .reg .u64 t; cvta.to.shared.u64 t, %1; cvt.u32.u64 %0, t; }" : "=r"(a) : "l"(p));
    return a;
}

/* ---------------- baseline-PTX tensor / async ops ---------------- */
__device__ __forceinline__ void ldsm_x4(uint32_t& a0, uint32_t& a1, uint32_t& a2,
                                        uint32_t& a3, uint32_t addr) {
    asm volatile("ldmatrix.sync.aligned.m8n8.x4.shared.b16 {%0,%1,%2,%3}, [%4];"
                 : "=r"(a0), "=r"(a1), "=r"(a2), "=r"(a3) : "r"(addr));
}
__device__ __forceinline__ void ldsm_x4_t(uint32_t& a0, uint32_t& a1, uint32_t& a2,
                                          uint32_t& a3, uint32_t addr) {
    asm volatile("ldmatrix.sync.aligned.m8n8.x4.trans.shared.b16 {%0,%1,%2,%3}, [%4];"
                 : "=r"(a0), "=r"(a1), "=r"(a2), "=r"(a3) : "r"(addr));
}
__device__ __forceinline__ void mma_bf16(float (&c)[4], const uint32_t (&a)[4],
                                         const uint32_t (&b)[2]) {
    asm volatile("mma.sync.aligned.m16n8k16.row.col.f32.bf16.bf16.f32 "
                 "{%0,%1,%2,%3}, {%4,%5,%6,%7}, {%8,%9}, {%0,%1,%2,%3};"
                 : "+f"(c[0]), "+f"(c[1]), "+f"(c[2]), "+f"(c[3])
                 : "r"(a[0]), "r"(a[1]), "r"(a[2]), "r"(a[3]), "r"(b[0]), "r"(b[1]));
}
#define CP16(dst, src) \
    asm volatile("cp.async.cg.shared.global [%0], [%1], 16;" :: "r"(dst), "l"(src))
#define CP_COMMIT() asm volatile("cp.async.commit_group;" ::: "memory")
#define CP_WAIT1()  asm volatile("cp.async.wait_group 1;" ::: "memory")
#define CP_WAIT0()  asm volatile("cp.async.wait_group 0;" ::: "memory")

__device__ __forceinline__ void split2(float a, float b, uint32_t& hi, uint32_t& lo) {
    bf16 ha = __float2bfloat16(a), hb = __float2bfloat16(b);
    bf16 la = __float2bfloat16(a - __bfloat162float(ha));
    bf16 lb = __float2bfloat16(b - __bfloat162float(hb));
    hi = ((uint32_t)__bfloat16_as_ushort(hb) << 16) | __bfloat16_as_ushort(ha);
    lo = ((uint32_t)__bfloat16_as_ushort(lb) << 16) | __bfloat16_as_ushort(la);
}

/* ---------------- preprocessing: fused split ---------------- */
#define SN0 (M_TOT*DIMC/4)
#define SN1 (3*DIMC*DIMC/4)
#define SN2 (DIMC*DIMC/4)

__global__ void split_all_kernel(const float* __restrict__ x,
                                 const float* __restrict__ wq,
                                 const float* __restrict__ wp) {
    int i = blockIdx.x * blockDim.x + threadIdx.x;
    int stride = gridDim.x * blockDim.x;
    const int total = SN0 + SN1 + SN2;
    for (; i < total; i += stride) {
        const float* s; bf16 *hp, *lp; int j = i;
        if (j < SN0)            { s = x;  hp = g_xh;  lp = g_xl; }
        else if (j < SN0 + SN1) { j -= SN0; s = wq; hp = g_wqh; lp = g_wql; }
        else                    { j -= SN0 + SN1; s = wp; hp = g_wph; lp = g_wpl; }
        float4 v = ((const float4*)s)[j];
        uint32_t h0, l0, h1, l1;
        split2(v.x, v.y, h0, l0);
        split2(v.z, v.w, h1, l1);
        ((uint2*)hp)[j] = make_uint2(h0, h1);
        ((uint2*)lp)[j] = make_uint2(l0, l1);
    }
}

/* single block, 1024 threads: sniff mask dtype, then per batch compact the
   unmasked key indices via a block prefix-scan. */
__global__ void mask_prep_kernel(const unsigned char* __restrict__ m) {
    __shared__ int sc[SEQ];
    __shared__ int s_any;
    const int tid = threadIdx.x;
    if (tid == 0) s_any = 0;
    __syncthreads();
    int loc = 0;
    for (int i = tid; i < BATCH*SEQ; i += SEQ)
        if ((i & 3) && m[i]) loc = 1;
    if (loc) s_any = 1;
    __syncthreads();
    const bool mbyte = (s_any != 0);
    const int* mi = (const int*)m;

    for (int b = 0; b < BATCH; b++) {
        bool masked = mbyte ? (m[b*SEQ + tid] != 0) : (mi[b*SEQ + tid] != 0);
        int flag = masked ? 0 : 1;
        sc[tid] = flag;
        __syncthreads();
        for (int off = 1; off < SEQ; off <<= 1) {
            int v = sc[tid];
            if (tid >= off) v += sc[tid - off];
            __syncthreads();
            sc[tid] = v;
            __syncthreads();
        }
        int incl = sc[tid];
        int cnt  = sc[SEQ-1];
        if (flag) g_kidx[b*SEQ + incl - 1] = tid;
        if (tid >= cnt) g_kidx[b*SEQ + tid] = 0;       /* pad: reuse row 0 */
        g_cmask[b*SEQ + tid] = (tid < cnt) ? 0.f : -1e30f;
        if (tid == 0) g_kcnt[b] = cnt;
        __syncthreads();
    }
}

/* ======================================================================
   cp.async double-buffered warp-MMA split-bf16 NT GEMM.
   CTA 128x128, 8 warps (2x4), warp 64x32. KC=32, 2 stages. 2 CTAs/SM.
   B fragments via ldmatrix.x4 pairs (nf -> {r0,r2}, nf+1 -> {r1,r3}).
   ====================================================================== */
#define KC2    32
#define NCH2   (768/KC2)          /* 24 */
#define GS     40                 /* halves per row (80 B) */
#define PLANE_B (128*GS*2)        /* 10240 B */
#define STAGE_B (4*PLANE_B)       /* 40960 B */
#define GEMM_SMEM (2*STAGE_B)     /* 81920 B */

template<int MODE>
__global__ void __launch_bounds__(256, 2) gemm_mma(
    const bf16* __restrict__ Ahg, const bf16* __restrict__ Alg,
    const bf16* __restrict__ Bhg, const bf16* __restrict__ Blg,
    const float* __restrict__ bias0, const float* __restrict__ bias1,
    float* __restrict__ Cout)
{
    extern __shared__ __align__(16) bf16 smb[];
    const uint32_t sb = smem_to_u32(smb);

    const int tid = threadIdx.x;
    const int lane = tid & 31;
    const int wid = tid >> 5;
    const int wm = wid >> 2, wn = wid & 3;
    const int bm = blockIdx.y * 128, bn = blockIdx.x * 128;

    const int a_row = lane & 15, a_cb = (lane >> 4) << 3;

    float acc[4][4][4];
#pragma unroll
    for (int i = 0; i < 4; i++)
#pragma unroll
        for (int j = 0; j < 4; j++)
#pragma unroll
            for (int t = 0; t < 4; t++) acc[i][j][t] = 0.f;

    auto issue = [&](int kc) {
        const int k0 = kc * KC2;
        const uint32_t st = sb + (uint32_t)((kc & 1) * STAGE_B);
#pragma unroll
        for (int u = 0; u < 8; u++) {
            int idx = tid + u * 256;
            int plane = idx >> 9;
            int rem = idx & 511;
            int row = rem >> 2;
            int c8 = (rem & 3) << 3;
            const bf16* gp = (plane == 0) ? Ahg : (plane == 1) ? Alg
                             : (plane == 2) ? Bhg : Blg;
            int rb = (plane < 2) ? bm : bn;
            uint32_t d = st + (uint32_t)(plane * PLANE_B) + (uint32_t)((row * GS + c8) * 2);
            CP16(d, gp + (size_t)(rb + row) * 768 + k0 + c8);
        }
        CP_COMMIT();
    };

    issue(0);
    for (int kc = 0; kc < NCH2; kc++) {
        if (kc + 1 < NCH2) { issue(kc + 1); CP_WAIT1(); }
        else               { CP_WAIT0(); }
        __syncthreads();

        const uint32_t st = sb + (uint32_t)((kc & 1) * STAGE_B);
        const uint32_t pAh = st, pAl = st + PLANE_B, pBh = st + 2*PLANE_B, pBl = st + 3*PLANE_B;
#pragma unroll
        for (int ks = 0; ks < 2; ks++) {
            const int kh = ks * 16;
            uint32_t af[4][4], bfr[4][2], bl2[4][2];
#pragma unroll
            for (int mf = 0; mf < 4; mf++) {
                uint32_t ad = pAh + (uint32_t)(((wm*64 + mf*16 + a_row) * GS + kh + a_cb) * 2);
                ldsm_x4(af[mf][0], af[mf][1], af[mf][2], af[mf][3], ad);
            }
#pragma unroll
            for (int np = 0; np < 2; np++) {
                uint32_t bd = pBh + (uint32_t)(((wn*32 + np*16 + a_row) * GS + kh + a_cb) * 2);
                uint32_t r0, r1, r2, r3;
                ldsm_x4(r0, r1, r2, r3, bd);
                bfr[2*np][0] = r0; bfr[2*np][1] = r2;
                bfr[2*np+1][0] = r1; bfr[2*np+1][1] = r3;
            }
#pragma unroll
            for (int mf = 0; mf < 4; mf++)
#pragma unroll
                for (int nf = 0; nf < 4; nf++)
                    mma_bf16(acc[mf][nf], af[mf], bfr[nf]);
#pragma unroll
            for (int np = 0; np < 2; np++) {
                uint32_t bd = pBl + (uint32_t)(((wn*32 + np*16 + a_row) * GS + kh + a_cb) * 2);
                uint32_t r0, r1, r2, r3;
                ldsm_x4(r0, r1, r2, r3, bd);
                bl2[2*np][0] = r0; bl2[2*np][1] = r2;
                bl2[2*np+1][0] = r1; bl2[2*np+1][1] = r3;
            }
#pragma unroll
            for (int mf = 0; mf < 4; mf++)
#pragma unroll
                for (int nf = 0; nf < 4; nf++)
                    mma_bf16(acc[mf][nf], af[mf], bl2[nf]);
#pragma unroll
            for (int mf = 0; mf < 4; mf++) {
                uint32_t ad = pAl + (uint32_t)(((wm*64 + mf*16 + a_row) * GS + kh + a_cb) * 2);
                ldsm_x4(af[mf][0], af[mf][1], af[mf][2], af[mf][3], ad);
            }
#pragma unroll
            for (int mf = 0; mf < 4; mf++)
#pragma unroll
                for (int nf = 0; nf < 4; nf++)
                    mma_bf16(acc[mf][nf], af[mf], bfr[nf]);
        }
        __syncthreads();
    }

    const int gr = lane >> 2;
    const int gc = (lane & 3) << 1;
#pragma unroll
    for (int mf = 0; mf < 4; mf++) {
#pragma unroll
        for (int nf = 0; nf < 4; nf++) {
            int n0 = bn + wn*32 + nf*8 + gc;
#pragma unroll
            for (int half = 0; half < 2; half++) {
                int m = bm + wm*64 + mf*16 + gr + half*8;
                float v0 = acc[mf][nf][half*2 + 0];
                float v1 = acc[mf][nf][half*2 + 1];
                if (MODE == 1) {
                    float2 o = make_float2(v0 + bias0[n0], v1 + bias0[n0+1]);
                    *(float2*)(Cout + (size_t)m * 768 + n0) = o;
                } else {
                    int which = n0 / 768;
                    int nn = n0 % 768;
                    int h = nn >> 6, d0 = nn & 63;
                    int b = m >> 10, tok = m & 1023;
                    if (which == 0) {
                        v0 = (v0 + bias0[nn])   * QK_SCALE;
                        v1 = (v1 + bias0[nn+1]) * QK_SCALE;
                    } else if (which == 2) {
                        v0 += bias1[nn];
                        v1 += bias1[nn+1];
                    }
                    uint32_t hp, lp;
                    split2(v0, v1, hp, lp);
                    size_t off = ((size_t)((b*NH + h)*SEQ + tok)) * HD + d0;
                    bf16* ph = (which == 0) ? g_qh : ((which == 1) ? g_kh : g_vh);
                    bf16* pl = (which == 0) ? g_ql : ((which == 1) ? g_kl : g_vl);
                    *(uint32_t*)(ph + off) = hp;
                    *(uint32_t*)(pl + off) = lp;
                }
            }
        }
    }
}

/* ======================================================================
   flash attention over COMPACTED keys (masked columns removed).
   128-thread CTA (4 warps x 16 q-rows), cp.async double-buffered K/V
   gathered through g_kidx; additive mask g_cmask handles ragged tail.
   ====================================================================== */
#define FS     72
#define FPLANE_B (64*FS*2)         /* 9216 B */
#define FSTAGE_B (4*FPLANE_B)      /* 36864 B */
#define FLASH_SMEM (2*FSTAGE_B)    /* 73728 B */

__global__ void __launch_bounds__(128, 3) flash_mma()
{
    extern __shared__ __align__(16) bf16 fsm[];
    const uint32_t sb = smem_to_u32(fsm);

    const int tid = threadIdx.x;
    const int lane = tid & 31;
    const int wid = tid >> 5;
    const int bh = blockIdx.y;
    const int qt = blockIdx.x;
    const int b = bh / NH, h = bh % NH;

    const size_t qbase = ((size_t)bh*SEQ + qt*64) * HD;
    const size_t kvbase = (size_t)bh*SEQ*HD;
    const int cnt = g_kcnt[b];
    const int ntiles = (cnt + 63) >> 6;
    const int* kidx = g_kidx + b*SEQ;

    /* ---- stage Q (2 planes; 8 uint4-slots/row) ---- */
#pragma unroll
    for (int u = 0; u < 8; u++) {
        int idx = tid + u * 128;
        int plane = idx >> 9;
        int rem = idx & 511;
        int row = rem >> 3;
        int c8 = (rem & 7) << 3;
        const bf16* src = plane ? g_ql : g_qh;
        *(uint4*)(fsm + plane*(64*FS) + row*FS + c8) =
            *(const uint4*)(src + qbase + (size_t)row*64 + c8);
    }
    __syncthreads();

    uint32_t qh[4][4], ql[4][4];
    {
        int row = wid*16 + (lane & 15);
        int cb = (lane >> 4) << 3;
#pragma unroll
        for (int ks = 0; ks < 4; ks++) {
            uint32_t off = (uint32_t)((row*FS + ks*16 + cb) * 2);
            ldsm_x4(qh[ks][0], qh[ks][1], qh[ks][2], qh[ks][3], sb + off);
            ldsm_x4(ql[ks][0], ql[ks][1], ql[ks][2], ql[ks][3],
                    sb + (uint32_t)FPLANE_B + off);
        }
    }
    __syncthreads();

    /* gather one compacted KV tile through the index */
    auto issue_kv = [&](int j) {
        const uint32_t st = sb + (uint32_t)((j & 1) * FSTAGE_B);
#pragma unroll
        for (int u = 0; u < 16; u++) {
            int idx = tid + u * 128;
            int plane = idx >> 9;
            int rem = idx & 511;
            int row = rem >> 3;
            int c8 = (rem & 7) << 3;
            int src_row = kidx[j*64 + row];
            const bf16* gp = (plane == 0) ? g_kh : (plane == 1) ? g_kl
                             : (plane == 2) ? g_vh : g_vl;
            uint32_t d = st + (uint32_t)(plane * FPLANE_B) + (uint32_t)((row*FS + c8) * 2);
            CP16(d, gp + kvbase + (size_t)src_row*64 + c8);
        }
        CP_COMMIT();
    };

    float o[8][4];
#pragma unroll
    for (int i = 0; i < 8; i++)
#pragma unroll
        for (int t = 0; t < 4; t++) o[i][t] = 0.f;
    float m0 = -1e30f, m1 = -1e30f, l0 = 0.f, l1 = 0.f;

    const int gr = lane >> 2;
    const int gc = (lane & 3) << 1;
    const int frow = lane & 15;
    const int fcb = (lane >> 4) << 3;

    issue_kv(0);
    for (int kt = 0; kt < ntiles; kt++) {
        float2 mk[8];
#pragma unroll
        for (int nf = 0; nf < 8; nf++)
            mk[nf] = *(const float2*)(g_cmask + b*SEQ + kt*64 + nf*8 + gc);

        if (kt + 1 < ntiles) { issue_kv(kt + 1); CP_WAIT1(); }
        else                 { CP_WAIT0(); }
        __syncthreads();

        const uint32_t st = sb + (uint32_t)((kt & 1) * FSTAGE_B);
        const uint32_t pKh = st, pKl = st + FPLANE_B;
        const uint32_t pVh = st + 2*FPLANE_B, pVl = st + 3*FPLANE_B;

        /* ---- S = (Qh+Ql)(Kh+Kl)^T, 3 wide passes per ks ---- */
        float s4[8][4];
#pragma unroll
        for (int i = 0; i < 8; i++)
#pragma unroll
            for (int t = 0; t < 4; t++) s4[i][t] = 0.f;

#pragma unroll
        for (int ks = 0; ks < 4; ks++) {
            uint32_t kbh[8][2], kbl[8][2];
#pragma unroll
            for (int np = 0; np < 4; np++) {
                uint32_t off = (uint32_t)(((np*16 + frow)*FS + ks*16 + fcb) * 2);
                uint32_t r0, r1, r2, r3;
                ldsm_x4(r0, r1, r2, r3, pKh + off);
                kbh[2*np][0] = r0; kbh[2*np][1] = r2;
                kbh[2*np+1][0] = r1; kbh[2*np+1][1] = r3;
                ldsm_x4(r0, r1, r2, r3, pKl + off);
                kbl[2*np][0] = r0; kbl[2*np][1] = r2;
                kbl[2*np+1][0] = r1; kbl[2*np+1][1] = r3;
            }
#pragma unroll
            for (int nf = 0; nf < 8; nf++) mma_bf16(s4[nf], qh[ks], kbh[nf]);
#pragma unroll
            for (int nf = 0; nf < 8; nf++) mma_bf16(s4[nf], ql[ks], kbh[nf]);
#pragma unroll
            for (int nf = 0; nf < 8; nf++) mma_bf16(s4[nf], qh[ks], kbl[nf]);
        }

        /* ---- mask + online softmax ---- */
        float tm0 = -1e30f, tm1 = -1e30f;
#pragma unroll
        for (int nf = 0; nf < 8; nf++) {
            s4[nf][0] += mk[nf].x; s4[nf][1] += mk[nf].y;
            s4[nf][2] += mk[nf].x; s4[nf][3] += mk[nf].y;
            tm0 = fmaxf(tm0, fmaxf(s4[nf][0], s4[nf][1]));
            tm1 = fmaxf(tm1, fmaxf(s4[nf][2], s4[nf][3]));
        }
        tm0 = fmaxf(tm0, __shfl_xor_sync(0xffffffffu, tm0, 1));
        tm0 = fmaxf(tm0, __shfl_xor_sync(0xffffffffu, tm0, 2));
        tm1 = fmaxf(tm1, __shfl_xor_sync(0xffffffffu, tm1, 1));
        tm1 = fmaxf(tm1, __shfl_xor_sync(0xffffffffu, tm1, 2));
        float mn0 = fmaxf(m0, tm0), mn1 = fmaxf(m1, tm1);
        float al0 = __expf(m0 - mn0), al1 = __expf(m1 - mn1);
        m0 = mn0; m1 = mn1;
        float ls0 = 0.f, ls1 = 0.f;
#pragma unroll
        for (int nf = 0; nf < 8; nf++) {
            s4[nf][0] = __expf(s4[nf][0] - mn0);
            s4[nf][1] = __expf(s4[nf][1] - mn0);
            s4[nf][2] = __expf(s4[nf][2] - mn1);
            s4[nf][3] = __expf(s4[nf][3] - mn1);
            ls0 += s4[nf][0] + s4[nf][1];
            ls1 += s4[nf][2] + s4[nf][3];
        }
        ls0 += __shfl_xor_sync(0xffffffffu, ls0, 1);
        ls0 += __shfl_xor_sync(0xffffffffu, ls0, 2);
        ls1 += __shfl_xor_sync(0xffffffffu, ls1, 1);
        ls1 += __shfl_xor_sync(0xffffffffu, ls1, 2);
        l0 = l0 * al0 + ls0;
        l1 = l1 * al1 + ls1;
#pragma unroll
        for (int nf = 0; nf < 8; nf++) {
            o[nf][0] *= al0; o[nf][1] *= al0;
            o[nf][2] *= al1; o[nf][3] *= al1;
        }

        /* ---- O += (Ph+Pl)(Vh+Vl), 3 wide passes per ksv ---- */
#pragma unroll
        for (int ksv = 0; ksv < 4; ksv++) {
            uint32_t ph[4], pl[4];
            split2(s4[2*ksv][0],   s4[2*ksv][1],   ph[0], pl[0]);
            split2(s4[2*ksv][2],   s4[2*ksv][3],   ph[1], pl[1]);
            split2(s4[2*ksv+1][0], s4[2*ksv+1][1], ph[2], pl[2]);
            split2(s4[2*ksv+1][2], s4[2*ksv+1][3], ph[3], pl[3]);
            uint32_t vhf[8][2], vlf[8][2];
#pragma unroll
            for (int np = 0; np < 4; np++) {
                uint32_t off = (uint32_t)(((ksv*16 + frow)*FS + np*16 + fcb) * 2);
                uint32_t r0, r1, r2, r3;
                ldsm_x4_t(r0, r1, r2, r3, pVh + off);
                vhf[2*np][0] = r0; vhf[2*np][1] = r1;
                vhf[2*np+1][0] = r2; vhf[2*np+1][1] = r3;
                ldsm_x4_t(r0, r1, r2, r3, pVl + off);
                vlf[2*np][0] = r0; vlf[2*np][1] = r1;
                vlf[2*np+1][0] = r2; vlf[2*np+1][1] = r3;
            }
#pragma unroll
            for (int nf = 0; nf < 8; nf++) mma_bf16(o[nf], ph, vhf[nf]);
#pragma unroll
            for (int nf = 0; nf < 8; nf++) mma_bf16(o[nf], ph, vlf[nf]);
#pragma unroll
            for (int nf = 0; nf < 8; nf++) mma_bf16(o[nf], pl, vhf[nf]);
        }
        __syncthreads();
    }

    /* ---- finalize ---- */
    float inv0 = 1.f / l0, inv1 = 1.f / l1;
    int tok0 = qt*64 + wid*16 + gr;
    size_t r0g = ((size_t)(b*SEQ + tok0)) * DIMC + h*HD;
    size_t r1g = r0g + 8*DIMC;
#pragma unroll
    for (int nf = 0; nf < 8; nf++) {
        int d = nf*8 + gc;
        uint32_t hp, lp;
        split2(o[nf][0]*inv0, o[nf][1]*inv0, hp, lp);
        *(uint32_t*)(g_aoh + r0g + d) = hp;
        *(uint32_t*)(g_aol + r0g + d) = lp;
        split2(o[nf][2]*inv1, o[nf][3]*inv1, hp, lp);
        *(uint32_t*)(g_aoh + r1g + d) = hp;
        *(uint32_t*)(g_aol + r1g + d) = lp;
    }
}

/* ---------------- launcher ---------------- */
extern "C" void kernel_launch(void* const* d_in, const int* in_sizes, int n_in,
                              void* d_out, int out_size)
{
    const float* x           = (const float*)d_in[0];
    const unsigned char* msk = (const unsigned char*)d_in[1];
    const float* qkv_w       = (const float*)d_in[2];
    const float* q_bias      = (const float*)d_in[3];
    const float* v_bias      = (const float*)d_in[4];
    const float* proj_w      = (const float*)d_in[5];
    const float* proj_b      = (const float*)d_in[6];
    float* out               = (float*)d_out;

    (void)in_sizes; (void)n_in; (void)out_size;

    cudaFuncSetAttribute(gemm_mma<0>, cudaFuncAttributeMaxDynamicSharedMemorySize, GEMM_SMEM);
    cudaFuncSetAttribute(gemm_mma<1>, cudaFuncAttributeMaxDynamicSharedMemorySize, GEMM_SMEM);
    cudaFuncSetAttribute(flash_mma, cudaFuncAttributeMaxDynamicSharedMemorySize, FLASH_SMEM);

    mask_prep_kernel<<<1, 1024>>>(msk);
    split_all_kernel<<<2048, 256>>>(x, qkv_w, proj_w);

    bf16 *xh, *xl, *wqh, *wql, *wph, *wpl;
    cudaGetSymbolAddress((void**)&xh,  g_xh);  cudaGetSymbolAddress((void**)&xl,  g_xl);
    cudaGetSymbolAddress((void**)&wqh, g_wqh); cudaGetSymbolAddress((void**)&wql, g_wql);
    cudaGetSymbolAddress((void**)&wph, g_wph); cudaGetSymbolAddress((void**)&wpl, g_wpl);

    gemm_mma<0><<<dim3(2304/128, M_TOT/128), 256, GEMM_SMEM>>>(
        xh, xl, wqh, wql, q_bias, v_bias, nullptr);

    flash_mma<<<dim3(SEQ/64, BH), 128, FLASH_SMEM>>>();

    bf16 *aoh, *aol;
    cudaGetSymbolAddress((void**)&aoh, g_aoh); cudaGetSymbolAddress((void**)&aol, g_aol);
    gemm_mma<1><<<dim3(768/128, M_TOT/128), 256, GEMM_SMEM>>>(
        aoh, aol, wph, wpl, proj_b, nullptr, out);
}